// round 2
// baseline (speedup 1.0000x reference)
#include <cuda_runtime.h>
#include <math.h>

// Problem-shape constants (fixed by the dataset): T=4096, H=2048, F=1408, E=8, K=2
constexpr int MAX_E = 8;
constexpr int MAX_T = 4096;
constexpr int MAX_F = 1408;

constexpr int BM = 64, BN = 64, BK = 16;   // GEMM tile
// 256 threads: 16x16 thread grid, each thread owns a 4x4 micro-tile.

// ---------------- scratch (no allocations allowed) ----------------
__device__ int   g_cnt[MAX_E];                         // per-expert token count
__device__ int   g_tok[MAX_E * MAX_T];                 // per-expert token list
__device__ float g_gw [MAX_E * MAX_T];                 // per-expert gate weight
__device__ float g_act_s[(size_t)MAX_T * MAX_F];       // shared-expert activation [T,F]
__device__ float g_act_e[(size_t)MAX_E * MAX_T * MAX_F]; // routed activations, per-expert slot [T,F]

// ---------------- kernel 0: zero counters ----------------
__global__ void zero_cnt_kernel() {
    if (threadIdx.x < MAX_E) g_cnt[threadIdx.x] = 0;
}

// ---------------- kernel 1: gating + top-2 routing ----------------
// One block per token; warp e computes dot(x[t], gate_w[e]).
__global__ void gate_kernel(const float* __restrict__ x,
                            const float* __restrict__ gw,
                            const float* __restrict__ bias,
                            int T, int Hd, int E) {
    int t = blockIdx.x;
    int w = threadIdx.x >> 5, lane = threadIdx.x & 31;
    __shared__ float sc[MAX_E];
    if (w < E) {
        const float* xr = x + (size_t)t * Hd;
        const float* gr = gw + (size_t)w * Hd;
        float s = 0.f;
        for (int i = lane; i < Hd; i += 32) s += xr[i] * gr[i];
        #pragma unroll
        for (int o = 16; o; o >>= 1) s += __shfl_down_sync(0xffffffffu, s, o);
        if (lane == 0) sc[w] = s;
    }
    __syncthreads();
    if (threadIdx.x == 0) {
        float score[MAX_E], rt[MAX_E];
        for (int e = 0; e < E; e++) {
            score[e] = 1.f / (1.f + expf(-sc[e]));
            rt[e] = score[e] + bias[e];
        }
        // top-2 on rt, first index wins ties (matches jax.lax.top_k)
        int b1 = 0;
        for (int e = 1; e < E; e++) if (rt[e] > rt[b1]) b1 = e;
        int b2 = -1;
        for (int e = 0; e < E; e++) {
            if (e == b1) continue;
            if (b2 < 0 || rt[e] > rt[b2]) b2 = e;
        }
        float s1 = score[b1], s2 = score[b2];
        float inv = 1.f / (s1 + s2);
        int p1 = atomicAdd(&g_cnt[b1], 1);
        g_tok[b1 * T + p1] = t; g_gw[b1 * T + p1] = s1 * inv;
        int p2 = atomicAdd(&g_cnt[b2], 1);
        g_tok[b2 * T + p2] = t; g_gw[b2 * T + p2] = s2 * inv;
    }
}

// ---------------- kernel 2/4: up-projection (dual GEMM + SwiGLU) ----------------
// act[r, n] = silu(X[r,:] . W1[n,:]) * (X[r,:] . W3[n,:])
// GATHER=false: shared expert, X rows are tokens 0..T-1, output g_act_s.
// GATHER=true:  expert e = blockIdx.z, rows gathered via g_tok, output g_act_e slot.
template <bool GATHER>
__global__ void __launch_bounds__(256)
up_kernel(const float* __restrict__ Xall,
          const float* __restrict__ W1all,
          const float* __restrict__ W3all,
          int T, int Hd, int F) {
    const int e = GATHER ? blockIdx.z : 0;
    const int valid = GATHER ? g_cnt[e] : T;
    const int row0 = blockIdx.y * BM;
    if (row0 >= valid) return;
    const int col0 = blockIdx.x * BN;

    const float* W1 = W1all + (size_t)e * F * Hd;
    const float* W3 = W3all + (size_t)e * F * Hd;
    float* ACT = GATHER ? (g_act_e + (size_t)e * T * F) : g_act_s;

    __shared__ float As [BK][BM];
    __shared__ float B1s[BK][BN];
    __shared__ float B3s[BK][BN];

    const int tid = threadIdx.x;
    const int lr = tid >> 2;            // 0..63
    const int lc = (tid & 3) * 4;       // 0,4,8,12

    int arow = row0 + lr;
    const float* Arow;
    if (GATHER) {
        int tk = (arow < valid) ? g_tok[e * T + arow] : 0;
        Arow = Xall + (size_t)tk * Hd;
    } else {
        Arow = Xall + (size_t)(arow < T ? arow : T - 1) * Hd;
    }
    const float* B1row = W1 + (size_t)(col0 + lr) * Hd;
    const float* B3row = W3 + (size_t)(col0 + lr) * Hd;

    const int tx = tid & 15, ty = tid >> 4;
    float acc1[4][4] = {}, acc3[4][4] = {};

    for (int k0 = 0; k0 < Hd; k0 += BK) {
        float4 a  = *(const float4*)(Arow  + k0 + lc);
        float4 b1 = *(const float4*)(B1row + k0 + lc);
        float4 b3 = *(const float4*)(B3row + k0 + lc);
        __syncthreads();
        As [lc+0][lr] = a.x;  As [lc+1][lr] = a.y;  As [lc+2][lr] = a.z;  As [lc+3][lr] = a.w;
        B1s[lc+0][lr] = b1.x; B1s[lc+1][lr] = b1.y; B1s[lc+2][lr] = b1.z; B1s[lc+3][lr] = b1.w;
        B3s[lc+0][lr] = b3.x; B3s[lc+1][lr] = b3.y; B3s[lc+2][lr] = b3.z; B3s[lc+3][lr] = b3.w;
        __syncthreads();
        #pragma unroll
        for (int kk = 0; kk < BK; kk++) {
            float av[4], bv1[4], bv3[4];
            #pragma unroll
            for (int i = 0; i < 4; i++) av[i]  = As [kk][ty * 4 + i];
            #pragma unroll
            for (int j = 0; j < 4; j++) { bv1[j] = B1s[kk][tx * 4 + j]; bv3[j] = B3s[kk][tx * 4 + j]; }
            #pragma unroll
            for (int i = 0; i < 4; i++)
                #pragma unroll
                for (int j = 0; j < 4; j++) {
                    acc1[i][j] = fmaf(av[i], bv1[j], acc1[i][j]);
                    acc3[i][j] = fmaf(av[i], bv3[j], acc3[i][j]);
                }
        }
    }

    #pragma unroll
    for (int i = 0; i < 4; i++) {
        int r = row0 + ty * 4 + i;
        if (r >= valid) continue;
        float* orow = ACT + (size_t)r * F + col0 + tx * 4;
        #pragma unroll
        for (int j = 0; j < 4; j++) {
            float h1 = acc1[i][j], h3 = acc3[i][j];
            float sv = h1 / (1.f + expf(-h1));   // silu
            orow[j] = sv * h3;
        }
    }
}

// ---------------- kernel 3/5: down-projection ----------------
// y[r, n] = ACT[r,:] . W2[n,:]   (K dim = F)
// SCATTER=false: shared expert, plain store into OUT (initializes d_out).
// SCATTER=true:  expert e = blockIdx.z, atomicAdd gate-weighted into OUT[token].
template <bool SCATTER>
__global__ void __launch_bounds__(256)
down_kernel(const float* __restrict__ W2all,
            float* __restrict__ OUT,
            int T, int Hd, int F) {
    const int e = SCATTER ? blockIdx.z : 0;
    const int valid = SCATTER ? g_cnt[e] : T;
    const int row0 = blockIdx.y * BM;
    if (row0 >= valid) return;
    const int col0 = blockIdx.x * BN;

    const float* ACT = SCATTER ? (g_act_e + (size_t)e * T * F) : g_act_s;
    const float* W2 = W2all + (size_t)e * Hd * F;

    __shared__ float As[BK][BM];
    __shared__ float Bs[BK][BN];

    const int tid = threadIdx.x;
    const int lr = tid >> 2;
    const int lc = (tid & 3) * 4;

    const float* Arow = ACT + (size_t)(row0 + lr) * F;   // rows >= valid read stale scratch; never stored
    const float* Brow = W2 + (size_t)(col0 + lr) * F;

    const int tx = tid & 15, ty = tid >> 4;
    float acc[4][4] = {};

    for (int k0 = 0; k0 < F; k0 += BK) {
        float4 a = *(const float4*)(Arow + k0 + lc);
        float4 b = *(const float4*)(Brow + k0 + lc);
        __syncthreads();
        As[lc+0][lr] = a.x; As[lc+1][lr] = a.y; As[lc+2][lr] = a.z; As[lc+3][lr] = a.w;
        Bs[lc+0][lr] = b.x; Bs[lc+1][lr] = b.y; Bs[lc+2][lr] = b.z; Bs[lc+3][lr] = b.w;
        __syncthreads();
        #pragma unroll
        for (int kk = 0; kk < BK; kk++) {
            float av[4], bv[4];
            #pragma unroll
            for (int i = 0; i < 4; i++) av[i] = As[kk][ty * 4 + i];
            #pragma unroll
            for (int j = 0; j < 4; j++) bv[j] = Bs[kk][tx * 4 + j];
            #pragma unroll
            for (int i = 0; i < 4; i++)
                #pragma unroll
                for (int j = 0; j < 4; j++)
                    acc[i][j] = fmaf(av[i], bv[j], acc[i][j]);
        }
    }

    #pragma unroll
    for (int i = 0; i < 4; i++) {
        int r = row0 + ty * 4 + i;
        if (r >= valid) continue;
        if (SCATTER) {
            int tk = g_tok[e * T + r];
            float g = g_gw[e * T + r];
            float* orow = OUT + (size_t)tk * Hd + col0 + tx * 4;
            #pragma unroll
            for (int j = 0; j < 4; j++) atomicAdd(&orow[j], g * acc[i][j]);
        } else {
            float* orow = OUT + (size_t)r * Hd + col0 + tx * 4;
            #pragma unroll
            for (int j = 0; j < 4; j++) orow[j] = acc[i][j];
        }
    }
}

// ---------------- launch ----------------
extern "C" void kernel_launch(void* const* d_in, const int* in_sizes, int n_in,
                              void* d_out, int out_size) {
    const float* x    = (const float*)d_in[0];  // [B,S,H]
    const float* gw   = (const float*)d_in[1];  // [E,H]
    const float* bias = (const float*)d_in[2];  // [E]
    const float* ws1  = (const float*)d_in[3];  // [F,H]
    const float* ws2  = (const float*)d_in[4];  // [H,F]
    const float* ws3  = (const float*)d_in[5];  // [F,H]
    const float* we1  = (const float*)d_in[6];  // [E,F,H]
    const float* we2  = (const float*)d_in[7];  // [E,H,F]
    const float* we3  = (const float*)d_in[8];  // [E,F,H]
    float* out = (float*)d_out;

    const int E  = in_sizes[2];
    const int Hd = in_sizes[1] / E;
    const int F  = in_sizes[3] / Hd;
    const int T  = in_sizes[0] / Hd;

    zero_cnt_kernel<<<1, 32>>>();
    gate_kernel<<<T, 256>>>(x, gw, bias, T, Hd, E);

    dim3 blk(256);
    dim3 gUpS(F / BN, (T + BM - 1) / BM);
    up_kernel<false><<<gUpS, blk>>>(x, ws1, ws3, T, Hd, F);

    dim3 gDnS(Hd / BN, (T + BM - 1) / BM);
    down_kernel<false><<<gDnS, blk>>>(ws2, out, T, Hd, F);

    dim3 gUpE(F / BN, (T + BM - 1) / BM, E);
    up_kernel<true><<<gUpE, blk>>>(x, we1, we3, T, Hd, F);

    dim3 gDnE(Hd / BN, (T + BM - 1) / BM, E);
    down_kernel<true><<<gDnE, blk>>>(we2, out, T, Hd, F);
}

// round 4
// speedup vs baseline: 2.3285x; 2.3285x over previous
#include <cuda_runtime.h>
#include <math.h>
#include <stdint.h>

// Shapes fixed by dataset: T=4096, H=2048, F=1408, E=8, K=2
constexpr int MAX_E = 8;
constexpr int MAX_T = 4096;
constexpr int MAX_F = 1408;

constexpr int BM = 128, BN = 64, BK = 32;
constexpr int SA = 36;  // padded smem row stride (floats) -> conflict-free fragment loads

// dynamic smem: up = A[2] + B1[2] + B3[2] + tok ; down = A[2] + B[2] + tok + gw
constexpr uint32_t A_TILE_U = 128 * SA;          // uints per A buffer
constexpr uint32_t B_TILE_U = 64 * SA;           // uints per B buffer
constexpr uint32_t UP_SMEM = (2 * A_TILE_U + 4 * B_TILE_U) * 4 + 512;
constexpr uint32_t DN_SMEM = (2 * A_TILE_U + 2 * B_TILE_U) * 4 + 1024;

// ---------------- scratch (no allocations allowed) ----------------
__device__ int   g_cnt[MAX_E];
__device__ int   g_tok[MAX_E * MAX_T];
__device__ float g_gw [MAX_E * MAX_T];
__device__ float g_act_s[(size_t)MAX_T * MAX_F];
__device__ float g_act_e[(size_t)MAX_E * MAX_T * MAX_F];

// ---------------- helpers ----------------
__device__ __forceinline__ uint4 tf32x4(float4 v) {
    uint4 u;
    asm("cvt.rna.tf32.f32 %0, %1;" : "=r"(u.x) : "f"(v.x));
    asm("cvt.rna.tf32.f32 %0, %1;" : "=r"(u.y) : "f"(v.y));
    asm("cvt.rna.tf32.f32 %0, %1;" : "=r"(u.z) : "f"(v.z));
    asm("cvt.rna.tf32.f32 %0, %1;" : "=r"(u.w) : "f"(v.w));
    return u;
}

__device__ __forceinline__ void mma8(float c[4], const uint32_t a[4], const uint32_t b[2]) {
    asm volatile(
        "mma.sync.aligned.m16n8k8.row.col.f32.tf32.tf32.f32 "
        "{%0,%1,%2,%3}, {%4,%5,%6,%7}, {%8,%9}, {%0,%1,%2,%3};"
        : "+f"(c[0]), "+f"(c[1]), "+f"(c[2]), "+f"(c[3])
        : "r"(a[0]), "r"(a[1]), "r"(a[2]), "r"(a[3]), "r"(b[0]), "r"(b[1]));
}

__device__ __forceinline__ float silu(float x) { return x / (1.f + __expf(-x)); }

// ---------------- kernel 0: zero counters ----------------
__global__ void zero_cnt_kernel() {
    if (threadIdx.x < MAX_E) g_cnt[threadIdx.x] = 0;
}

// ---------------- kernel 1: gating + top-2 routing ----------------
__global__ void gate_kernel(const float* __restrict__ x,
                            const float* __restrict__ gw,
                            const float* __restrict__ bias,
                            int T, int Hd, int E) {
    int t = blockIdx.x;
    int w = threadIdx.x >> 5, lane = threadIdx.x & 31;
    __shared__ float sc[MAX_E];
    if (w < E) {
        const float* xr = x + (size_t)t * Hd;
        const float* gr = gw + (size_t)w * Hd;
        float s = 0.f;
        for (int i = lane; i < Hd; i += 32) s += xr[i] * gr[i];
        #pragma unroll
        for (int o = 16; o; o >>= 1) s += __shfl_down_sync(0xffffffffu, s, o);
        if (lane == 0) sc[w] = s;
    }
    __syncthreads();
    if (threadIdx.x == 0) {
        float score[MAX_E], rt[MAX_E];
        for (int e = 0; e < E; e++) {
            score[e] = 1.f / (1.f + expf(-sc[e]));
            rt[e] = score[e] + bias[e];
        }
        int b1 = 0;
        for (int e = 1; e < E; e++) if (rt[e] > rt[b1]) b1 = e;
        int b2 = -1;
        for (int e = 0; e < E; e++) {
            if (e == b1) continue;
            if (b2 < 0 || rt[e] > rt[b2]) b2 = e;
        }
        float s1 = score[b1], s2 = score[b2];
        float inv = 1.f / (s1 + s2);
        int p1 = atomicAdd(&g_cnt[b1], 1);
        g_tok[b1 * T + p1] = t; g_gw[b1 * T + p1] = s1 * inv;
        int p2 = atomicAdd(&g_cnt[b2], 1);
        g_tok[b2 * T + p2] = t; g_gw[b2 * T + p2] = s2 * inv;
    }
}

// ---------------- up-projection: dual tf32 mma.sync + fused SwiGLU ----------------
// ACT[r, n] = silu(X[r]·W1[n]) * (X[r]·W3[n]);  M=128 rows, N=64 cols, K=H
template<bool ROUTED>
__global__ void __launch_bounds__(256, 1)
up_mma(const float* __restrict__ X, const float* __restrict__ W1a, const float* __restrict__ W3a,
       int T, int H, int F)
{
    extern __shared__ __align__(16) uint32_t sm[];
    const int e     = ROUTED ? blockIdx.z : 0;
    const int valid = ROUTED ? g_cnt[e] : T;
    const int row0  = blockIdx.y * BM;
    if (row0 >= valid) return;
    const int col0  = blockIdx.x * BN;
    const int tid   = threadIdx.x, lane = tid & 31, wid = tid >> 5;
    const int wm    = wid >> 1, wn = wid & 1, grp = lane >> 2, tig = lane & 3;

    uint32_t* As [2] = { sm,                          sm + A_TILE_U };
    uint32_t* B1s[2] = { sm + 2*A_TILE_U,             sm + 2*A_TILE_U + B_TILE_U };
    uint32_t* B3s[2] = { sm + 2*A_TILE_U + 2*B_TILE_U, sm + 2*A_TILE_U + 3*B_TILE_U };
    int* stok = (int*)(sm + 2*A_TILE_U + 4*B_TILE_U);

    if (ROUTED && tid < 128) {
        int i = row0 + tid; if (i >= valid) i = valid - 1;
        stok[tid] = g_tok[e * T + i];
    }
    __syncthreads();

    const float* W1 = W1a + (size_t)e * F * H;
    const float* W3 = W3a + (size_t)e * F * H;
    float* ACT = ROUTED ? (g_act_e + (size_t)e * T * F) : g_act_s;

    // global->smem mapping: thread covers rows r4+32i, cols c4*4..c4*4+3 of the k-chunk
    const int r4 = tid >> 3, c4 = tid & 7;
    const float* asrc[4];
    uint32_t astO[4];
    #pragma unroll
    for (int i = 0; i < 4; i++) {
        int r = r4 + 32 * i;
        int tok = ROUTED ? stok[r] : (row0 + r);
        asrc[i] = X + (size_t)tok * H + c4 * 4;
        astO[i] = r * SA + c4 * 4;
    }
    const float* b1src[2]; const float* b3src[2]; uint32_t bstO[2];
    #pragma unroll
    for (int i = 0; i < 2; i++) {
        int r = r4 + 32 * i;   // r4 in 0..31 -> rows 0..63
        b1src[i] = W1 + (size_t)(col0 + r) * H + c4 * 4;
        b3src[i] = W3 + (size_t)(col0 + r) * H + c4 * 4;
        bstO[i] = r * SA + c4 * 4;
    }

    float acc1[2][4][4] = {}, acc3[2][4][4] = {};
    float4 ra[4], rb1[2], rb3[2];
    const int nch = H / BK;

    // prologue: chunk 0
    #pragma unroll
    for (int i = 0; i < 4; i++) ra[i]  = *(const float4*)(asrc[i]);
    #pragma unroll
    for (int i = 0; i < 2; i++) { rb1[i] = *(const float4*)(b1src[i]); rb3[i] = *(const float4*)(b3src[i]); }
    #pragma unroll
    for (int i = 0; i < 4; i++) *(uint4*)(As[0]  + astO[i]) = tf32x4(ra[i]);
    #pragma unroll
    for (int i = 0; i < 2; i++) { *(uint4*)(B1s[0] + bstO[i]) = tf32x4(rb1[i]);
                                  *(uint4*)(B3s[0] + bstO[i]) = tf32x4(rb3[i]); }
    __syncthreads();

    for (int c = 0; c < nch; ++c) {
        const int s = c & 1;
        if (c + 1 < nch) {
            const int k0 = (c + 1) * BK;
            #pragma unroll
            for (int i = 0; i < 4; i++) ra[i]  = *(const float4*)(asrc[i] + k0);
            #pragma unroll
            for (int i = 0; i < 2; i++) { rb1[i] = *(const float4*)(b1src[i] + k0);
                                          rb3[i] = *(const float4*)(b3src[i] + k0); }
        }
        #pragma unroll
        for (int j = 0; j < 4; j++) {
            uint32_t af[2][4];
            #pragma unroll
            for (int mt = 0; mt < 2; mt++) {
                const uint32_t* p = As[s] + (wm * 32 + mt * 16 + grp) * SA + 8 * j + tig;
                af[mt][0] = p[0]; af[mt][1] = p[8 * SA]; af[mt][2] = p[4]; af[mt][3] = p[8 * SA + 4];
            }
            #pragma unroll
            for (int nt = 0; nt < 4; nt++) {
                const uint32_t* q1 = B1s[s] + (wn * 32 + nt * 8 + grp) * SA + 8 * j + tig;
                const uint32_t* q3 = B3s[s] + (wn * 32 + nt * 8 + grp) * SA + 8 * j + tig;
                uint32_t bf1[2] = { q1[0], q1[4] };
                uint32_t bf3[2] = { q3[0], q3[4] };
                #pragma unroll
                for (int mt = 0; mt < 2; mt++) {
                    mma8(acc1[mt][nt], af[mt], bf1);
                    mma8(acc3[mt][nt], af[mt], bf3);
                }
            }
        }
        if (c + 1 < nch) {
            const int ns = s ^ 1;
            #pragma unroll
            for (int i = 0; i < 4; i++) *(uint4*)(As[ns]  + astO[i]) = tf32x4(ra[i]);
            #pragma unroll
            for (int i = 0; i < 2; i++) { *(uint4*)(B1s[ns] + bstO[i]) = tf32x4(rb1[i]);
                                          *(uint4*)(B3s[ns] + bstO[i]) = tf32x4(rb3[i]); }
            __syncthreads();
        }
    }

    // epilogue: SwiGLU in registers, float2 stores
    #pragma unroll
    for (int mt = 0; mt < 2; mt++) {
        #pragma unroll
        for (int nt = 0; nt < 4; nt++) {
            int rA = row0 + wm * 32 + mt * 16 + grp;
            int cA = col0 + wn * 32 + nt * 8 + 2 * tig;
            if (rA < valid) {
                float2 o;
                o.x = silu(acc1[mt][nt][0]) * acc3[mt][nt][0];
                o.y = silu(acc1[mt][nt][1]) * acc3[mt][nt][1];
                *(float2*)(ACT + (size_t)rA * F + cA) = o;
            }
            int rB = rA + 8;
            if (rB < valid) {
                float2 o;
                o.x = silu(acc1[mt][nt][2]) * acc3[mt][nt][2];
                o.y = silu(acc1[mt][nt][3]) * acc3[mt][nt][3];
                *(float2*)(ACT + (size_t)rB * F + cA) = o;
            }
        }
    }
}

// ---------------- down-projection: tf32 mma.sync, plain store or gated scatter ----------------
template<bool ROUTED>
__global__ void __launch_bounds__(256, 1)
down_mma(const float* __restrict__ W2a, float* __restrict__ OUT, int T, int H, int F)
{
    extern __shared__ __align__(16) uint32_t sm[];
    const int e     = ROUTED ? blockIdx.z : 0;
    const int valid = ROUTED ? g_cnt[e] : T;
    const int row0  = blockIdx.y * BM;
    if (row0 >= valid) return;
    const int col0  = blockIdx.x * BN;
    const int tid   = threadIdx.x, lane = tid & 31, wid = tid >> 5;
    const int wm    = wid >> 1, wn = wid & 1, grp = lane >> 2, tig = lane & 3;

    uint32_t* As[2] = { sm,              sm + A_TILE_U };
    uint32_t* Bs[2] = { sm + 2*A_TILE_U, sm + 2*A_TILE_U + B_TILE_U };
    int*   stok = (int*)  (sm + 2*A_TILE_U + 2*B_TILE_U);
    float* sgw  = (float*)(sm + 2*A_TILE_U + 2*B_TILE_U + 128);

    if (ROUTED && tid < 128) {
        int i = row0 + tid; if (i >= valid) i = valid - 1;
        stok[tid] = g_tok[e * T + i];
        sgw[tid]  = g_gw [e * T + i];
    }
    __syncthreads();

    const float* ACT = ROUTED ? (g_act_e + (size_t)e * T * F) : g_act_s;
    const float* W2  = W2a + (size_t)e * H * F;

    const int r4 = tid >> 3, c4 = tid & 7;
    const float* asrc[4]; uint32_t astO[4];
    #pragma unroll
    for (int i = 0; i < 4; i++) {
        int r = r4 + 32 * i;
        asrc[i] = ACT + (size_t)(row0 + r) * F + c4 * 4;   // rows >= valid: stale finite scratch, discarded
        astO[i] = r * SA + c4 * 4;
    }
    const float* bsrc[2]; uint32_t bstO[2];
    #pragma unroll
    for (int i = 0; i < 2; i++) {
        int r = r4 + 32 * i;
        bsrc[i] = W2 + (size_t)(col0 + r) * F + c4 * 4;
        bstO[i] = r * SA + c4 * 4;
    }

    float acc[2][4][4] = {};
    float4 ra[4], rb[2];
    const int nch = F / BK;

    #pragma unroll
    for (int i = 0; i < 4; i++) ra[i] = *(const float4*)(asrc[i]);
    #pragma unroll
    for (int i = 0; i < 2; i++) rb[i] = *(const float4*)(bsrc[i]);
    #pragma unroll
    for (int i = 0; i < 4; i++) *(uint4*)(As[0] + astO[i]) = tf32x4(ra[i]);
    #pragma unroll
    for (int i = 0; i < 2; i++) *(uint4*)(Bs[0] + bstO[i]) = tf32x4(rb[i]);
    __syncthreads();

    for (int c = 0; c < nch; ++c) {
        const int s = c & 1;
        if (c + 1 < nch) {
            const int k0 = (c + 1) * BK;
            #pragma unroll
            for (int i = 0; i < 4; i++) ra[i] = *(const float4*)(asrc[i] + k0);
            #pragma unroll
            for (int i = 0; i < 2; i++) rb[i] = *(const float4*)(bsrc[i] + k0);
        }
        #pragma unroll
        for (int j = 0; j < 4; j++) {
            uint32_t af[2][4];
            #pragma unroll
            for (int mt = 0; mt < 2; mt++) {
                const uint32_t* p = As[s] + (wm * 32 + mt * 16 + grp) * SA + 8 * j + tig;
                af[mt][0] = p[0]; af[mt][1] = p[8 * SA]; af[mt][2] = p[4]; af[mt][3] = p[8 * SA + 4];
            }
            #pragma unroll
            for (int nt = 0; nt < 4; nt++) {
                const uint32_t* q = Bs[s] + (wn * 32 + nt * 8 + grp) * SA + 8 * j + tig;
                uint32_t bf[2] = { q[0], q[4] };
                #pragma unroll
                for (int mt = 0; mt < 2; mt++) mma8(acc[mt][nt], af[mt], bf);
            }
        }
        if (c + 1 < nch) {
            const int ns = s ^ 1;
            #pragma unroll
            for (int i = 0; i < 4; i++) *(uint4*)(As[ns] + astO[i]) = tf32x4(ra[i]);
            #pragma unroll
            for (int i = 0; i < 2; i++) *(uint4*)(Bs[ns] + bstO[i]) = tf32x4(rb[i]);
            __syncthreads();
        }
    }

    #pragma unroll
    for (int mt = 0; mt < 2; mt++) {
        #pragma unroll
        for (int nt = 0; nt < 4; nt++) {
            int cA = col0 + wn * 32 + nt * 8 + 2 * tig;
            #pragma unroll
            for (int half = 0; half < 2; half++) {
                int rloc = wm * 32 + mt * 16 + grp + 8 * half;
                int r = row0 + rloc;
                if (r >= valid) continue;
                float v0 = acc[mt][nt][2 * half], v1 = acc[mt][nt][2 * half + 1];
                if (!ROUTED) {
                    float2 o; o.x = v0; o.y = v1;
                    *(float2*)(OUT + (size_t)r * H + cA) = o;
                } else {
                    int tok = stok[rloc]; float g = sgw[rloc];
                    float* dst = OUT + (size_t)tok * H + cA;
                    atomicAdd(dst,     g * v0);
                    atomicAdd(dst + 1, g * v1);
                }
            }
        }
    }
}

// ---------------- launch ----------------
extern "C" void kernel_launch(void* const* d_in, const int* in_sizes, int n_in,
                              void* d_out, int out_size) {
    const float* x    = (const float*)d_in[0];
    const float* gw   = (const float*)d_in[1];
    const float* bias = (const float*)d_in[2];
    const float* ws1  = (const float*)d_in[3];
    const float* ws2  = (const float*)d_in[4];
    const float* ws3  = (const float*)d_in[5];
    const float* we1  = (const float*)d_in[6];
    const float* we2  = (const float*)d_in[7];
    const float* we3  = (const float*)d_in[8];
    float* out = (float*)d_out;

    const int E  = in_sizes[2];
    const int Hd = in_sizes[1] / E;
    const int F  = in_sizes[3] / Hd;
    const int T  = in_sizes[0] / Hd;

    cudaFuncSetAttribute(up_mma<false>,   cudaFuncAttributeMaxDynamicSharedMemorySize, UP_SMEM);
    cudaFuncSetAttribute(up_mma<true>,    cudaFuncAttributeMaxDynamicSharedMemorySize, UP_SMEM);
    cudaFuncSetAttribute(down_mma<false>, cudaFuncAttributeMaxDynamicSharedMemorySize, DN_SMEM);
    cudaFuncSetAttribute(down_mma<true>,  cudaFuncAttributeMaxDynamicSharedMemorySize, DN_SMEM);

    zero_cnt_kernel<<<1, 32>>>();
    gate_kernel<<<T, 256>>>(x, gw, bias, T, Hd, E);

    dim3 blk(256);
    up_mma<false><<<dim3(F / BN, T / BM), blk, UP_SMEM>>>(x, ws1, ws3, T, Hd, F);
    down_mma<false><<<dim3(Hd / BN, T / BM), blk, DN_SMEM>>>(ws2, out, T, Hd, F);
    up_mma<true><<<dim3(F / BN, T / BM, E), blk, UP_SMEM>>>(x, we1, we3, T, Hd, F);
    down_mma<true><<<dim3(Hd / BN, T / BM, E), blk, DN_SMEM>>>(we2, out, T, Hd, F);
}

// round 6
// speedup vs baseline: 2.9296x; 1.2581x over previous
#include <cuda_runtime.h>
#include <math.h>
#include <stdint.h>

// Shapes fixed by dataset: T=4096, H=2048, F=1408, E=8, K=2
constexpr int MAX_E = 8;
constexpr int MAX_T = 4096;
constexpr int MAX_F = 1408;
constexpr int MAX_H = 2048;

constexpr int BM = 128, BN = 64, BK = 32;
constexpr int SA = 36;                    // padded smem row stride (words)
constexpr uint32_t A_TILE_U = 128 * SA;   // 4608 words (18432 B)
constexpr uint32_t B_TILE_U = 64 * SA;    // 2304 words (9216 B)
constexpr uint32_t A_BYTES = A_TILE_U * 4;
constexpr uint32_t B_BYTES = B_TILE_U * 4;
constexpr uint32_t UP_STAGE_U = A_TILE_U + 2 * B_TILE_U;   // 9216 words
constexpr uint32_t DN_STAGE_U = A_TILE_U + B_TILE_U;       // 6912 words
constexpr uint32_t UP_STAGE_B = UP_STAGE_U * 4;            // 36864
constexpr uint32_t DN_STAGE_B = DN_STAGE_U * 4;            // 27648
constexpr uint32_t UP_SMEM = 3 * UP_STAGE_B + 512;         // 111104
constexpr uint32_t DN_SMEM = 3 * DN_STAGE_B + 1024;        // 83968

// ---------------- scratch (static; no allocations allowed) ----------------
__device__ int      g_cnt[MAX_E];
__device__ int      g_tok[MAX_E * MAX_T];
__device__ float    g_gw [MAX_E * MAX_T];
__device__ uint32_t g_act_s[(size_t)MAX_T * MAX_F];            // tf32-rounded act
__device__ uint32_t g_act_e[(size_t)MAX_E * MAX_T * MAX_F];
// tf32-rounded copies of inputs
__device__ uint32_t c_x  [(size_t)MAX_T * MAX_H];
__device__ uint32_t c_ws1[(size_t)MAX_F * MAX_H];
__device__ uint32_t c_ws3[(size_t)MAX_F * MAX_H];
__device__ uint32_t c_ws2[(size_t)MAX_H * MAX_F];
__device__ uint32_t c_we1[(size_t)MAX_E * MAX_F * MAX_H];
__device__ uint32_t c_we3[(size_t)MAX_E * MAX_F * MAX_H];
__device__ uint32_t c_we2[(size_t)MAX_E * MAX_H * MAX_F];

// ---------------- helpers ----------------
__device__ __forceinline__ uint32_t s2u(const void* p) {
    uint32_t a;
    asm("{ .reg .u64 t; cvta.to.shared.u64 t, %1; cvt.u32.u64 %0, t; }" : "=r"(a) : "l"(p));
    return a;
}
__device__ __forceinline__ uint4 tf32x4(float4 v) {
    uint4 u;
    asm("cvt.rna.tf32.f32 %0, %1;" : "=r"(u.x) : "f"(v.x));
    asm("cvt.rna.tf32.f32 %0, %1;" : "=r"(u.y) : "f"(v.y));
    asm("cvt.rna.tf32.f32 %0, %1;" : "=r"(u.z) : "f"(v.z));
    asm("cvt.rna.tf32.f32 %0, %1;" : "=r"(u.w) : "f"(v.w));
    return u;
}
__device__ __forceinline__ uint32_t tf32_1(float v) {
    uint32_t u;
    asm("cvt.rna.tf32.f32 %0, %1;" : "=r"(u) : "f"(v));
    return u;
}
__device__ __forceinline__ void mma8(float c[4], const uint32_t a[4], const uint32_t b[2]) {
    asm volatile(
        "mma.sync.aligned.m16n8k8.row.col.f32.tf32.tf32.f32 "
        "{%0,%1,%2,%3}, {%4,%5,%6,%7}, {%8,%9}, {%0,%1,%2,%3};"
        : "+f"(c[0]), "+f"(c[1]), "+f"(c[2]), "+f"(c[3])
        : "r"(a[0]), "r"(a[1]), "r"(a[2]), "r"(a[3]), "r"(b[0]), "r"(b[1]));
}
__device__ __forceinline__ void cpa16(uint32_t dst, const uint32_t* src) {
    asm volatile("cp.async.cg.shared.global [%0], [%1], 16;" :: "r"(dst), "l"(src));
}
#define CP_COMMIT() asm volatile("cp.async.commit_group;" ::: "memory")
#define CP_WAIT1()  asm volatile("cp.async.wait_group 1;" ::: "memory")
__device__ __forceinline__ float silu(float x) { return x / (1.f + __expf(-x)); }

// ---------------- kernel: tf32-round a tensor ----------------
__global__ void conv_kernel(const float* __restrict__ in, uint32_t* __restrict__ out, size_t n) {
    size_t i = ((size_t)blockIdx.x * blockDim.x + threadIdx.x) * 4;
    if (i < n) *(uint4*)(out + i) = tf32x4(*(const float4*)(in + i));
}

// ---------------- kernel: zero counters ----------------
__global__ void zero_cnt_kernel() {
    if (threadIdx.x < MAX_E) g_cnt[threadIdx.x] = 0;
}

// ---------------- kernel: gating + top-2 routing ----------------
__global__ void gate_kernel(const float* __restrict__ x,
                            const float* __restrict__ gw,
                            const float* __restrict__ bias,
                            int T, int Hd, int E) {
    int t = blockIdx.x;
    int w = threadIdx.x >> 5, lane = threadIdx.x & 31;
    __shared__ float sc[MAX_E];
    if (w < E) {
        const float* xr = x + (size_t)t * Hd;
        const float* gr = gw + (size_t)w * Hd;
        float s = 0.f;
        for (int i = lane; i < Hd; i += 32) s += xr[i] * gr[i];
        #pragma unroll
        for (int o = 16; o; o >>= 1) s += __shfl_down_sync(0xffffffffu, s, o);
        if (lane == 0) sc[w] = s;
    }
    __syncthreads();
    if (threadIdx.x == 0) {
        float score[MAX_E], rt[MAX_E];
        for (int e = 0; e < E; e++) {
            score[e] = 1.f / (1.f + expf(-sc[e]));
            rt[e] = score[e] + bias[e];
        }
        int b1 = 0;
        for (int e = 1; e < E; e++) if (rt[e] > rt[b1]) b1 = e;
        int b2 = -1;
        for (int e = 0; e < E; e++) {
            if (e == b1) continue;
            if (b2 < 0 || rt[e] > rt[b2]) b2 = e;
        }
        float s1 = score[b1], s2 = score[b2];
        float inv = 1.f / (s1 + s2);
        int p1 = atomicAdd(&g_cnt[b1], 1);
        g_tok[b1 * T + p1] = t; g_gw[b1 * T + p1] = s1 * inv;
        int p2 = atomicAdd(&g_cnt[b2], 1);
        g_tok[b2 * T + p2] = t; g_gw[b2 * T + p2] = s2 * inv;
    }
}

// ---------------- up-projection: dual tf32 mma + fused SwiGLU ----------------
// 512 threads, 16 warps in 4x4 grid; warp tile 32x16; block tile 128x64x32.
template<bool ROUTED>
__global__ void __launch_bounds__(512, 1)
up_mma(const uint32_t* __restrict__ X, const uint32_t* __restrict__ W1a,
       const uint32_t* __restrict__ W3a, int T, int H, int F)
{
    extern __shared__ __align__(16) uint32_t sm[];
    const int e     = ROUTED ? blockIdx.z : 0;
    const int valid = ROUTED ? g_cnt[e] : T;
    const int row0  = blockIdx.y * BM;
    if (row0 >= valid) return;
    const int col0  = blockIdx.x * BN;
    const int tid   = threadIdx.x, lane = tid & 31, wid = tid >> 5;
    const int wm    = wid >> 2, wn = wid & 3, grp = lane >> 2, tig = lane & 3;
    const uint32_t sb = s2u(sm);

    int* stok = (int*)(sm + 3 * UP_STAGE_U);
    if (ROUTED && tid < 128) {
        int i = row0 + tid; if (i >= valid) i = valid - 1;
        stok[tid] = g_tok[e * T + i];
    }
    __syncthreads();

    const uint32_t* W1 = W1a + (size_t)e * F * H;
    const uint32_t* W3 = W3a + (size_t)e * F * H;
    uint32_t* ACT = ROUTED ? (g_act_e + (size_t)e * T * F) : g_act_s;

    // cp.async mapping: 512 threads; A rows r8,r8+64; B rows r8 (0..63); 16B each
    const int r8 = tid >> 3, c4 = tid & 7;
    const uint32_t* asrc[2]; uint32_t aoffB[2];
    #pragma unroll
    for (int i = 0; i < 2; i++) {
        int r = r8 + 64 * i;
        int tok = ROUTED ? stok[r] : (row0 + r);
        asrc[i] = X + (size_t)tok * H + c4 * 4;
        aoffB[i] = (uint32_t)(r * SA + c4 * 4) * 4;
    }
    const uint32_t* b1src = W1 + (size_t)(col0 + r8) * H + c4 * 4;
    const uint32_t* b3src = W3 + (size_t)(col0 + r8) * H + c4 * 4;
    const uint32_t boffB = (uint32_t)(r8 * SA + c4 * 4) * 4;

    const int nch = H / BK;
    auto load_stage = [&](int c) {
        uint32_t dbase = sb + (uint32_t)(c % 3) * UP_STAGE_B;
        int k0 = c * BK;
        cpa16(dbase + aoffB[0], asrc[0] + k0);
        cpa16(dbase + aoffB[1], asrc[1] + k0);
        cpa16(dbase + A_BYTES + boffB, b1src + k0);
        cpa16(dbase + A_BYTES + B_BYTES + boffB, b3src + k0);
    };

    float acc1[2][2][4] = {}, acc3[2][2][4] = {};

    load_stage(0); CP_COMMIT();
    load_stage(1); CP_COMMIT();

    for (int c = 0; c < nch; ++c) {
        CP_WAIT1();
        __syncthreads();
        if (c + 2 < nch) load_stage(c + 2);
        CP_COMMIT();

        const uint32_t* As  = sm + (c % 3) * UP_STAGE_U;
        const uint32_t* B1s = As + A_TILE_U;
        const uint32_t* B3s = As + A_TILE_U + B_TILE_U;
        #pragma unroll
        for (int j = 0; j < 4; j++) {
            uint32_t af[2][4];
            #pragma unroll
            for (int mt = 0; mt < 2; mt++) {
                const uint32_t* p = As + (wm * 32 + mt * 16 + grp) * SA + 8 * j + tig;
                af[mt][0] = p[0]; af[mt][1] = p[8 * SA]; af[mt][2] = p[4]; af[mt][3] = p[8 * SA + 4];
            }
            #pragma unroll
            for (int nt = 0; nt < 2; nt++) {
                const uint32_t* q1 = B1s + (wn * 16 + nt * 8 + grp) * SA + 8 * j + tig;
                const uint32_t* q3 = B3s + (wn * 16 + nt * 8 + grp) * SA + 8 * j + tig;
                uint32_t bf1[2] = { q1[0], q1[4] };
                uint32_t bf3[2] = { q3[0], q3[4] };
                #pragma unroll
                for (int mt = 0; mt < 2; mt++) {
                    mma8(acc1[mt][nt], af[mt], bf1);
                    mma8(acc3[mt][nt], af[mt], bf3);
                }
            }
        }
    }

    // epilogue: SwiGLU, store tf32-rounded pairs
    #pragma unroll
    for (int mt = 0; mt < 2; mt++) {
        #pragma unroll
        for (int nt = 0; nt < 2; nt++) {
            int cA = col0 + wn * 16 + nt * 8 + 2 * tig;
            #pragma unroll
            for (int half = 0; half < 2; half++) {
                int r = row0 + wm * 32 + mt * 16 + grp + 8 * half;
                if (r >= valid) continue;
                float ox = silu(acc1[mt][nt][2 * half])     * acc3[mt][nt][2 * half];
                float oy = silu(acc1[mt][nt][2 * half + 1]) * acc3[mt][nt][2 * half + 1];
                uint2 u; u.x = tf32_1(ox); u.y = tf32_1(oy);
                *(uint2*)(ACT + (size_t)r * F + cA) = u;
            }
        }
    }
}

// ---------------- down-projection: tf32 mma, plain store or gated scatter ----------------
template<bool ROUTED>
__global__ void __launch_bounds__(512, 1)
down_mma(const uint32_t* __restrict__ W2a, float* __restrict__ OUT, int T, int H, int F)
{
    extern __shared__ __align__(16) uint32_t sm[];
    const int e     = ROUTED ? blockIdx.z : 0;
    const int valid = ROUTED ? g_cnt[e] : T;
    const int row0  = blockIdx.y * BM;
    if (row0 >= valid) return;
    const int col0  = blockIdx.x * BN;
    const int tid   = threadIdx.x, lane = tid & 31, wid = tid >> 5;
    const int wm    = wid >> 2, wn = wid & 3, grp = lane >> 2, tig = lane & 3;
    const uint32_t sb = s2u(sm);

    int*   stok = (int*)  (sm + 3 * DN_STAGE_U);
    float* sgw  = (float*)(sm + 3 * DN_STAGE_U + 128);
    if (ROUTED && tid < 128) {
        int i = row0 + tid; if (i >= valid) i = valid - 1;
        stok[tid] = g_tok[e * T + i];
        sgw[tid]  = g_gw [e * T + i];
    }
    __syncthreads();

    const uint32_t* ACT = ROUTED ? (g_act_e + (size_t)e * T * F) : g_act_s;
    const uint32_t* W2  = W2a + (size_t)e * H * F;

    const int r8 = tid >> 3, c4 = tid & 7;
    const uint32_t* asrc[2]; uint32_t aoffB[2];
    #pragma unroll
    for (int i = 0; i < 2; i++) {
        int r = r8 + 64 * i;
        asrc[i] = ACT + (size_t)(row0 + r) * F + c4 * 4;   // rows >= valid: stale finite scratch, discarded
        aoffB[i] = (uint32_t)(r * SA + c4 * 4) * 4;
    }
    const uint32_t* bsrc = W2 + (size_t)(col0 + r8) * F + c4 * 4;
    const uint32_t boffB = (uint32_t)(r8 * SA + c4 * 4) * 4;

    const int nch = F / BK;
    auto load_stage = [&](int c) {
        uint32_t dbase = sb + (uint32_t)(c % 3) * DN_STAGE_B;
        int k0 = c * BK;
        cpa16(dbase + aoffB[0], asrc[0] + k0);
        cpa16(dbase + aoffB[1], asrc[1] + k0);
        cpa16(dbase + A_BYTES + boffB, bsrc + k0);
    };

    float acc[2][2][4] = {};

    load_stage(0); CP_COMMIT();
    load_stage(1); CP_COMMIT();

    for (int c = 0; c < nch; ++c) {
        CP_WAIT1();
        __syncthreads();
        if (c + 2 < nch) load_stage(c + 2);
        CP_COMMIT();

        const uint32_t* As = sm + (c % 3) * DN_STAGE_U;
        const uint32_t* Bs = As + A_TILE_U;
        #pragma unroll
        for (int j = 0; j < 4; j++) {
            uint32_t af[2][4];
            #pragma unroll
            for (int mt = 0; mt < 2; mt++) {
                const uint32_t* p = As + (wm * 32 + mt * 16 + grp) * SA + 8 * j + tig;
                af[mt][0] = p[0]; af[mt][1] = p[8 * SA]; af[mt][2] = p[4]; af[mt][3] = p[8 * SA + 4];
            }
            #pragma unroll
            for (int nt = 0; nt < 2; nt++) {
                const uint32_t* q = Bs + (wn * 16 + nt * 8 + grp) * SA + 8 * j + tig;
                uint32_t bf[2] = { q[0], q[4] };
                #pragma unroll
                for (int mt = 0; mt < 2; mt++) mma8(acc[mt][nt], af[mt], bf);
            }
        }
    }

    #pragma unroll
    for (int mt = 0; mt < 2; mt++) {
        #pragma unroll
        for (int nt = 0; nt < 2; nt++) {
            int cA = col0 + wn * 16 + nt * 8 + 2 * tig;
            #pragma unroll
            for (int half = 0; half < 2; half++) {
                int rloc = wm * 32 + mt * 16 + grp + 8 * half;
                int r = row0 + rloc;
                if (r >= valid) continue;
                float v0 = acc[mt][nt][2 * half], v1 = acc[mt][nt][2 * half + 1];
                if (!ROUTED) {
                    float2 o; o.x = v0; o.y = v1;
                    *(float2*)(OUT + (size_t)r * H + cA) = o;
                } else {
                    int tok = stok[rloc]; float g = sgw[rloc];
                    float* dst = OUT + (size_t)tok * H + cA;
                    atomicAdd(dst,     g * v0);
                    atomicAdd(dst + 1, g * v1);
                }
            }
        }
    }
}

// ---------------- launch ----------------
extern "C" void kernel_launch(void* const* d_in, const int* in_sizes, int n_in,
                              void* d_out, int out_size) {
    const float* x    = (const float*)d_in[0];
    const float* gw   = (const float*)d_in[1];
    const float* bias = (const float*)d_in[2];
    const float* ws1  = (const float*)d_in[3];
    const float* ws2  = (const float*)d_in[4];
    const float* ws3  = (const float*)d_in[5];
    const float* we1  = (const float*)d_in[6];
    const float* we2  = (const float*)d_in[7];
    const float* we3  = (const float*)d_in[8];
    float* out = (float*)d_out;

    const int E  = in_sizes[2];
    const int Hd = in_sizes[1] / E;
    const int F  = in_sizes[3] / Hd;
    const int T  = in_sizes[0] / Hd;

    cudaFuncSetAttribute(up_mma<false>,   cudaFuncAttributeMaxDynamicSharedMemorySize, UP_SMEM);
    cudaFuncSetAttribute(up_mma<true>,    cudaFuncAttributeMaxDynamicSharedMemorySize, UP_SMEM);
    cudaFuncSetAttribute(down_mma<false>, cudaFuncAttributeMaxDynamicSharedMemorySize, DN_SMEM);
    cudaFuncSetAttribute(down_mma<true>,  cudaFuncAttributeMaxDynamicSharedMemorySize, DN_SMEM);

    // device-symbol addresses (host side)
    uint32_t *p_cx, *p_cws1, *p_cws3, *p_cws2, *p_cwe1, *p_cwe3, *p_cwe2;
    cudaGetSymbolAddress((void**)&p_cx,   c_x);
    cudaGetSymbolAddress((void**)&p_cws1, c_ws1);
    cudaGetSymbolAddress((void**)&p_cws3, c_ws3);
    cudaGetSymbolAddress((void**)&p_cws2, c_ws2);
    cudaGetSymbolAddress((void**)&p_cwe1, c_we1);
    cudaGetSymbolAddress((void**)&p_cwe3, c_we3);
    cudaGetSymbolAddress((void**)&p_cwe2, c_we2);

    zero_cnt_kernel<<<1, 32>>>();
    gate_kernel<<<T, 256>>>(x, gw, bias, T, Hd, E);

    auto conv = [&](const float* in, uint32_t* o, size_t n) {
        conv_kernel<<<(unsigned)((n / 4 + 255) / 256), 256>>>(in, o, n);
    };
    conv(x,   p_cx,   (size_t)T * Hd);
    conv(ws1, p_cws1, (size_t)F * Hd);
    conv(ws3, p_cws3, (size_t)F * Hd);
    conv(ws2, p_cws2, (size_t)Hd * F);
    conv(we1, p_cwe1, (size_t)E * F * Hd);
    conv(we3, p_cwe3, (size_t)E * F * Hd);
    conv(we2, p_cwe2, (size_t)E * Hd * F);

    dim3 blk(512);
    up_mma<false><<<dim3(F / BN, T / BM), blk, UP_SMEM>>>(p_cx, p_cws1, p_cws3, T, Hd, F);
    down_mma<false><<<dim3(Hd / BN, T / BM), blk, DN_SMEM>>>(p_cws2, out, T, Hd, F);
    up_mma<true><<<dim3(F / BN, T / BM, E), blk, UP_SMEM>>>(p_cx, p_cwe1, p_cwe3, T, Hd, F);
    down_mma<true><<<dim3(Hd / BN, T / BM, E), blk, DN_SMEM>>>(p_cwe2, out, T, Hd, F);
}

// round 7
// speedup vs baseline: 3.2507x; 1.1096x over previous
#include <cuda_runtime.h>
#include <math.h>
#include <stdint.h>

// Shapes fixed by dataset: T=4096, H=2048, F=1408, E=8, K=2
constexpr int MAX_E = 8;
constexpr int MAX_T = 4096;
constexpr int MAX_F = 1408;
constexpr int MAX_H = 2048;

constexpr int BM = 128, BN = 64, BK = 32;
constexpr int SA = 36;                    // padded smem row stride (words)
constexpr uint32_t A_TILE_U = 128 * SA;
constexpr uint32_t B_TILE_U = 64 * SA;
constexpr uint32_t A_BYTES = A_TILE_U * 4;
constexpr uint32_t B_BYTES = B_TILE_U * 4;
constexpr uint32_t UP_STAGE_U = A_TILE_U + 2 * B_TILE_U;
constexpr uint32_t DN_STAGE_U = A_TILE_U + B_TILE_U;
constexpr uint32_t UP_STAGE_B = UP_STAGE_U * 4;
constexpr uint32_t DN_STAGE_B = DN_STAGE_U * 4;
constexpr uint32_t UP_SMEM = 3 * UP_STAGE_B + 512;    // 111104
constexpr uint32_t DN_SMEM = 3 * DN_STAGE_B + 1024;   // 83968 -> 2 CTAs/SM

// ---------------- scratch (static; no allocations allowed) ----------------
__device__ int      g_cnt[MAX_E];
__device__ int      g_tok[MAX_E * MAX_T];
__device__ float    g_gw [MAX_E * MAX_T];
__device__ uint32_t g_act_s[(size_t)MAX_T * MAX_F];
__device__ uint32_t g_act_e[(size_t)MAX_E * MAX_T * MAX_F];
__device__ uint32_t c_x  [(size_t)MAX_T * MAX_H];
__device__ uint32_t c_ws1[(size_t)MAX_F * MAX_H];
__device__ uint32_t c_ws3[(size_t)MAX_F * MAX_H];
__device__ uint32_t c_ws2[(size_t)MAX_H * MAX_F];
__device__ uint32_t c_we1[(size_t)MAX_E * MAX_F * MAX_H];
__device__ uint32_t c_we3[(size_t)MAX_E * MAX_F * MAX_H];
__device__ uint32_t c_we2[(size_t)MAX_E * MAX_H * MAX_F];

// ---------------- helpers ----------------
__device__ __forceinline__ uint32_t s2u(const void* p) {
    uint32_t a;
    asm("{ .reg .u64 t; cvta.to.shared.u64 t, %1; cvt.u32.u64 %0, t; }" : "=r"(a) : "l"(p));
    return a;
}
__device__ __forceinline__ uint4 tf32x4(float4 v) {
    uint4 u;
    asm("cvt.rna.tf32.f32 %0, %1;" : "=r"(u.x) : "f"(v.x));
    asm("cvt.rna.tf32.f32 %0, %1;" : "=r"(u.y) : "f"(v.y));
    asm("cvt.rna.tf32.f32 %0, %1;" : "=r"(u.z) : "f"(v.z));
    asm("cvt.rna.tf32.f32 %0, %1;" : "=r"(u.w) : "f"(v.w));
    return u;
}
__device__ __forceinline__ uint32_t tf32_1(float v) {
    uint32_t u;
    asm("cvt.rna.tf32.f32 %0, %1;" : "=r"(u) : "f"(v));
    return u;
}
__device__ __forceinline__ void mma8(float c[4], const uint32_t a[4], const uint32_t b[2]) {
    asm volatile(
        "mma.sync.aligned.m16n8k8.row.col.f32.tf32.tf32.f32 "
        "{%0,%1,%2,%3}, {%4,%5,%6,%7}, {%8,%9}, {%0,%1,%2,%3};"
        : "+f"(c[0]), "+f"(c[1]), "+f"(c[2]), "+f"(c[3])
        : "r"(a[0]), "r"(a[1]), "r"(a[2]), "r"(a[3]), "r"(b[0]), "r"(b[1]));
}
__device__ __forceinline__ void cpa16(uint32_t dst, const uint32_t* src) {
    asm volatile("cp.async.cg.shared.global [%0], [%1], 16;" :: "r"(dst), "l"(src));
}
#define CP_COMMIT() asm volatile("cp.async.commit_group;" ::: "memory")
#define CP_WAIT1()  asm volatile("cp.async.wait_group 1;" ::: "memory")
__device__ __forceinline__ float silu(float x) { return x / (1.f + __expf(-x)); }

// ---------------- kernel: tf32-round a tensor ----------------
__global__ void conv_kernel(const float* __restrict__ in, uint32_t* __restrict__ out, size_t n) {
    size_t i = ((size_t)blockIdx.x * blockDim.x + threadIdx.x) * 4;
    if (i < n) *(uint4*)(out + i) = tf32x4(*(const float4*)(in + i));
}

// ---------------- kernel: zero counters ----------------
__global__ void zero_cnt_kernel() {
    if (threadIdx.x < MAX_E) g_cnt[threadIdx.x] = 0;
}

// ---------------- kernel: gating + top-2 routing ----------------
__global__ void gate_kernel(const float* __restrict__ x,
                            const float* __restrict__ gw,
                            const float* __restrict__ bias,
                            int T, int Hd, int E) {
    int t = blockIdx.x;
    int w = threadIdx.x >> 5, lane = threadIdx.x & 31;
    __shared__ float sc[MAX_E];
    if (w < E) {
        const float* xr = x + (size_t)t * Hd;
        const float* gr = gw + (size_t)w * Hd;
        float s = 0.f;
        for (int i = lane; i < Hd; i += 32) s += xr[i] * gr[i];
        #pragma unroll
        for (int o = 16; o; o >>= 1) s += __shfl_down_sync(0xffffffffu, s, o);
        if (lane == 0) sc[w] = s;
    }
    __syncthreads();
    if (threadIdx.x == 0) {
        float score[MAX_E], rt[MAX_E];
        for (int e = 0; e < E; e++) {
            score[e] = 1.f / (1.f + expf(-sc[e]));
            rt[e] = score[e] + bias[e];
        }
        int b1 = 0;
        for (int e = 1; e < E; e++) if (rt[e] > rt[b1]) b1 = e;
        int b2 = -1;
        for (int e = 0; e < E; e++) {
            if (e == b1) continue;
            if (b2 < 0 || rt[e] > rt[b2]) b2 = e;
        }
        float s1 = score[b1], s2 = score[b2];
        float inv = 1.f / (s1 + s2);
        int p1 = atomicAdd(&g_cnt[b1], 1);
        g_tok[b1 * T + p1] = t; g_gw[b1 * T + p1] = s1 * inv;
        int p2 = atomicAdd(&g_cnt[b2], 1);
        g_tok[b2 * T + p2] = t; g_gw[b2 * T + p2] = s2 * inv;
    }
}

// ---------------- up-projection: dual tf32 mma + fused SwiGLU ----------------
// 256 threads, 8 fat warps (4x2); warp tile 32x32 per pipe; block 128x64x32.
template<bool ROUTED>
__global__ void __launch_bounds__(256, 1)
up_mma(const uint32_t* __restrict__ X, const uint32_t* __restrict__ W1a,
       const uint32_t* __restrict__ W3a, int T, int H, int F)
{
    extern __shared__ __align__(16) uint32_t sm[];
    const int e     = ROUTED ? blockIdx.z : 0;
    const int valid = ROUTED ? g_cnt[e] : T;
    const int row0  = blockIdx.y * BM;
    if (row0 >= valid) return;
    const int col0  = blockIdx.x * BN;
    const int tid   = threadIdx.x, lane = tid & 31, wid = tid >> 5;
    const int wm    = wid >> 1, wn = wid & 1, grp = lane >> 2, tig = lane & 3;
    const uint32_t sb = s2u(sm);

    int* stok = (int*)(sm + 3 * UP_STAGE_U);
    if (ROUTED && tid < 128) {
        int i = row0 + tid; if (i >= valid) i = valid - 1;
        stok[tid] = g_tok[e * T + i];
    }
    __syncthreads();

    const uint32_t* W1 = W1a + (size_t)e * F * H;
    const uint32_t* W3 = W3a + (size_t)e * F * H;
    uint32_t* ACT = ROUTED ? (g_act_e + (size_t)e * T * F) : g_act_s;

    // cp.async: 256 threads, 16B each: A rows r+32i (i<4), B rows r+32i (i<2)
    const int r32 = tid >> 3, c4 = tid & 7;
    const uint32_t* asrc[4]; uint32_t aoffB[4];
    #pragma unroll
    for (int i = 0; i < 4; i++) {
        int r = r32 + 32 * i;
        int tok = ROUTED ? stok[r] : (row0 + r);
        asrc[i] = X + (size_t)tok * H + c4 * 4;
        aoffB[i] = (uint32_t)(r * SA + c4 * 4) * 4;
    }
    const uint32_t* b1src[2]; const uint32_t* b3src[2]; uint32_t boffB[2];
    #pragma unroll
    for (int i = 0; i < 2; i++) {
        int r = r32 + 32 * i;
        b1src[i] = W1 + (size_t)(col0 + r) * H + c4 * 4;
        b3src[i] = W3 + (size_t)(col0 + r) * H + c4 * 4;
        boffB[i] = (uint32_t)(r * SA + c4 * 4) * 4;
    }

    const int nch = H / BK;
    auto load_stage = [&](int c) {
        uint32_t dbase = sb + (uint32_t)(c % 3) * UP_STAGE_B;
        int k0 = c * BK;
        #pragma unroll
        for (int i = 0; i < 4; i++) cpa16(dbase + aoffB[i], asrc[i] + k0);
        #pragma unroll
        for (int i = 0; i < 2; i++) {
            cpa16(dbase + A_BYTES + boffB[i], b1src[i] + k0);
            cpa16(dbase + A_BYTES + B_BYTES + boffB[i], b3src[i] + k0);
        }
    };

    float acc1[2][4][4] = {}, acc3[2][4][4] = {};

    load_stage(0); CP_COMMIT();
    load_stage(1); CP_COMMIT();

    for (int c = 0; c < nch; ++c) {
        CP_WAIT1();
        __syncthreads();
        if (c + 2 < nch) load_stage(c + 2);
        CP_COMMIT();

        const uint32_t* As  = sm + (c % 3) * UP_STAGE_U;
        const uint32_t* B1s = As + A_TILE_U;
        const uint32_t* B3s = As + A_TILE_U + B_TILE_U;
        #pragma unroll
        for (int j = 0; j < 4; j++) {
            uint32_t af[2][4];
            #pragma unroll
            for (int mt = 0; mt < 2; mt++) {
                const uint32_t* p = As + (wm * 32 + mt * 16 + grp) * SA + 8 * j + tig;
                af[mt][0] = p[0]; af[mt][1] = p[8 * SA]; af[mt][2] = p[4]; af[mt][3] = p[8 * SA + 4];
            }
            #pragma unroll
            for (int nt = 0; nt < 4; nt++) {
                const uint32_t* q1 = B1s + (wn * 32 + nt * 8 + grp) * SA + 8 * j + tig;
                const uint32_t* q3 = B3s + (wn * 32 + nt * 8 + grp) * SA + 8 * j + tig;
                uint32_t bf1[2] = { q1[0], q1[4] };
                uint32_t bf3[2] = { q3[0], q3[4] };
                #pragma unroll
                for (int mt = 0; mt < 2; mt++) {
                    mma8(acc1[mt][nt], af[mt], bf1);
                    mma8(acc3[mt][nt], af[mt], bf3);
                }
            }
        }
    }

    // epilogue: SwiGLU, store tf32-rounded pairs
    #pragma unroll
    for (int mt = 0; mt < 2; mt++) {
        #pragma unroll
        for (int nt = 0; nt < 4; nt++) {
            int cA = col0 + wn * 32 + nt * 8 + 2 * tig;
            #pragma unroll
            for (int half = 0; half < 2; half++) {
                int r = row0 + wm * 32 + mt * 16 + grp + 8 * half;
                if (r >= valid) continue;
                float ox = silu(acc1[mt][nt][2 * half])     * acc3[mt][nt][2 * half];
                float oy = silu(acc1[mt][nt][2 * half + 1]) * acc3[mt][nt][2 * half + 1];
                uint2 u; u.x = tf32_1(ox); u.y = tf32_1(oy);
                *(uint2*)(ACT + (size_t)r * F + cA) = u;
            }
        }
    }
}

// ---------------- down-projection: tf32 mma, plain store or gated scatter ----------------
// 256 threads, 8 fat warps (4x2); warp tile 32x32; 2 CTAs/SM.
template<bool ROUTED>
__global__ void __launch_bounds__(256, 2)
down_mma(const uint32_t* __restrict__ W2a, float* __restrict__ OUT, int T, int H, int F)
{
    extern __shared__ __align__(16) uint32_t sm[];
    const int e     = ROUTED ? blockIdx.z : 0;
    const int valid = ROUTED ? g_cnt[e] : T;
    const int row0  = blockIdx.y * BM;
    if (row0 >= valid) return;
    const int col0  = blockIdx.x * BN;
    const int tid   = threadIdx.x, lane = tid & 31, wid = tid >> 5;
    const int wm    = wid >> 1, wn = wid & 1, grp = lane >> 2, tig = lane & 3;
    const uint32_t sb = s2u(sm);

    int*   stok = (int*)  (sm + 3 * DN_STAGE_U);
    float* sgw  = (float*)(sm + 3 * DN_STAGE_U + 128);
    if (ROUTED && tid < 128) {
        int i = row0 + tid; if (i >= valid) i = valid - 1;
        stok[tid] = g_tok[e * T + i];
        sgw[tid]  = g_gw [e * T + i];
    }
    __syncthreads();

    const uint32_t* ACT = ROUTED ? (g_act_e + (size_t)e * T * F) : g_act_s;
    const uint32_t* W2  = W2a + (size_t)e * H * F;

    const int r32 = tid >> 3, c4 = tid & 7;
    const uint32_t* asrc[4]; uint32_t aoffB[4];
    #pragma unroll
    for (int i = 0; i < 4; i++) {
        int r = r32 + 32 * i;
        asrc[i] = ACT + (size_t)(row0 + r) * F + c4 * 4;   // rows >= valid: stale finite scratch, discarded
        aoffB[i] = (uint32_t)(r * SA + c4 * 4) * 4;
    }
    const uint32_t* bsrc[2]; uint32_t boffB[2];
    #pragma unroll
    for (int i = 0; i < 2; i++) {
        int r = r32 + 32 * i;
        bsrc[i] = W2 + (size_t)(col0 + r) * F + c4 * 4;
        boffB[i] = (uint32_t)(r * SA + c4 * 4) * 4;
    }

    const int nch = F / BK;
    auto load_stage = [&](int c) {
        uint32_t dbase = sb + (uint32_t)(c % 3) * DN_STAGE_B;
        int k0 = c * BK;
        #pragma unroll
        for (int i = 0; i < 4; i++) cpa16(dbase + aoffB[i], asrc[i] + k0);
        #pragma unroll
        for (int i = 0; i < 2; i++) cpa16(dbase + A_BYTES + boffB[i], bsrc[i] + k0);
    };

    float acc[2][4][4] = {};

    load_stage(0); CP_COMMIT();
    load_stage(1); CP_COMMIT();

    for (int c = 0; c < nch; ++c) {
        CP_WAIT1();
        __syncthreads();
        if (c + 2 < nch) load_stage(c + 2);
        CP_COMMIT();

        const uint32_t* As = sm + (c % 3) * DN_STAGE_U;
        const uint32_t* Bs = As + A_TILE_U;
        #pragma unroll
        for (int j = 0; j < 4; j++) {
            uint32_t af[2][4];
            #pragma unroll
            for (int mt = 0; mt < 2; mt++) {
                const uint32_t* p = As + (wm * 32 + mt * 16 + grp) * SA + 8 * j + tig;
                af[mt][0] = p[0]; af[mt][1] = p[8 * SA]; af[mt][2] = p[4]; af[mt][3] = p[8 * SA + 4];
            }
            #pragma unroll
            for (int nt = 0; nt < 4; nt++) {
                const uint32_t* q = Bs + (wn * 32 + nt * 8 + grp) * SA + 8 * j + tig;
                uint32_t bf[2] = { q[0], q[4] };
                #pragma unroll
                for (int mt = 0; mt < 2; mt++) mma8(acc[mt][nt], af[mt], bf);
            }
        }
    }

    #pragma unroll
    for (int mt = 0; mt < 2; mt++) {
        #pragma unroll
        for (int nt = 0; nt < 4; nt++) {
            int cA = col0 + wn * 32 + nt * 8 + 2 * tig;
            #pragma unroll
            for (int half = 0; half < 2; half++) {
                int rloc = wm * 32 + mt * 16 + grp + 8 * half;
                int r = row0 + rloc;
                if (r >= valid) continue;
                float v0 = acc[mt][nt][2 * half], v1 = acc[mt][nt][2 * half + 1];
                if (!ROUTED) {
                    float2 o; o.x = v0; o.y = v1;
                    *(float2*)(OUT + (size_t)r * H + cA) = o;
                } else {
                    int tok = stok[rloc]; float g = sgw[rloc];
                    float* dst = OUT + (size_t)tok * H + cA;
                    atomicAdd(dst,     g * v0);
                    atomicAdd(dst + 1, g * v1);
                }
            }
        }
    }
}

// ---------------- launch ----------------
extern "C" void kernel_launch(void* const* d_in, const int* in_sizes, int n_in,
                              void* d_out, int out_size) {
    const float* x    = (const float*)d_in[0];
    const float* gw   = (const float*)d_in[1];
    const float* bias = (const float*)d_in[2];
    const float* ws1  = (const float*)d_in[3];
    const float* ws2  = (const float*)d_in[4];
    const float* ws3  = (const float*)d_in[5];
    const float* we1  = (const float*)d_in[6];
    const float* we2  = (const float*)d_in[7];
    const float* we3  = (const float*)d_in[8];
    float* out = (float*)d_out;

    const int E  = in_sizes[2];
    const int Hd = in_sizes[1] / E;
    const int F  = in_sizes[3] / Hd;
    const int T  = in_sizes[0] / Hd;

    cudaFuncSetAttribute(up_mma<false>,   cudaFuncAttributeMaxDynamicSharedMemorySize, UP_SMEM);
    cudaFuncSetAttribute(up_mma<true>,    cudaFuncAttributeMaxDynamicSharedMemorySize, UP_SMEM);
    cudaFuncSetAttribute(down_mma<false>, cudaFuncAttributeMaxDynamicSharedMemorySize, DN_SMEM);
    cudaFuncSetAttribute(down_mma<true>,  cudaFuncAttributeMaxDynamicSharedMemorySize, DN_SMEM);

    uint32_t *p_cx, *p_cws1, *p_cws3, *p_cws2, *p_cwe1, *p_cwe3, *p_cwe2;
    cudaGetSymbolAddress((void**)&p_cx,   c_x);
    cudaGetSymbolAddress((void**)&p_cws1, c_ws1);
    cudaGetSymbolAddress((void**)&p_cws3, c_ws3);
    cudaGetSymbolAddress((void**)&p_cws2, c_ws2);
    cudaGetSymbolAddress((void**)&p_cwe1, c_we1);
    cudaGetSymbolAddress((void**)&p_cwe3, c_we3);
    cudaGetSymbolAddress((void**)&p_cwe2, c_we2);

    zero_cnt_kernel<<<1, 32>>>();
    gate_kernel<<<T, 256>>>(x, gw, bias, T, Hd, E);

    auto conv = [&](const float* in, uint32_t* o, size_t n) {
        conv_kernel<<<(unsigned)((n / 4 + 255) / 256), 256>>>(in, o, n);
    };
    conv(x,   p_cx,   (size_t)T * Hd);
    conv(ws1, p_cws1, (size_t)F * Hd);
    conv(ws3, p_cws3, (size_t)F * Hd);
    conv(ws2, p_cws2, (size_t)Hd * F);
    conv(we1, p_cwe1, (size_t)E * F * Hd);
    conv(we3, p_cwe3, (size_t)E * F * Hd);
    conv(we2, p_cwe2, (size_t)E * Hd * F);

    dim3 blk(256);
    up_mma<false><<<dim3(F / BN, T / BM), blk, UP_SMEM>>>(p_cx, p_cws1, p_cws3, T, Hd, F);
    down_mma<false><<<dim3(Hd / BN, T / BM), blk, DN_SMEM>>>(p_cws2, out, T, Hd, F);
    up_mma<true><<<dim3(F / BN, T / BM, E), blk, UP_SMEM>>>(p_cx, p_cwe1, p_cwe3, T, Hd, F);
    down_mma<true><<<dim3(Hd / BN, T / BM, E), blk, DN_SMEM>>>(p_cwe2, out, T, Hd, F);
}

// round 8
// speedup vs baseline: 3.8033x; 1.1700x over previous
#include <cuda_runtime.h>
#include <math.h>
#include <stdint.h>

// Shapes fixed by dataset: T=4096, H=2048, F=1408, E=8, K=2
constexpr int MAX_E = 8;
constexpr int MAX_T = 4096;
constexpr int MAX_F = 1408;
constexpr int MAX_H = 2048;

constexpr int BM = 128, BK = 32;
constexpr int SA = 36;                       // padded smem row stride (words)
constexpr uint32_t A_TILE_U  = 128 * SA;     // 4608 words
constexpr uint32_t B64_U     = 64 * SA;      // 2304 words
constexpr uint32_t B128_U    = 128 * SA;     // 4608 words
constexpr uint32_t A_BYTES   = A_TILE_U * 4;
constexpr uint32_t UP_STAGE_U = A_TILE_U + 2 * B64_U;   // 9216 words
constexpr uint32_t DN_STAGE_U = A_TILE_U + B128_U;      // 9216 words
constexpr uint32_t UP_STAGE_B = UP_STAGE_U * 4;         // 36864
constexpr uint32_t DN_STAGE_B = DN_STAGE_U * 4;
constexpr uint32_t UP_SMEM = 3 * UP_STAGE_B + 512;      // 111104 -> 2 CTAs/SM
constexpr uint32_t DN_SMEM = 3 * DN_STAGE_B + 1024;     // 111616 -> 2 CTAs/SM

// ---------------- scratch (static; no allocations allowed) ----------------
__device__ int      g_cnt[MAX_E];
__device__ int      g_tok[MAX_E * MAX_T];
__device__ float    g_gw [MAX_E * MAX_T];
__device__ uint32_t g_act_s[(size_t)MAX_T * MAX_F];
__device__ uint32_t g_act_e[(size_t)MAX_E * MAX_T * MAX_F];
__device__ uint32_t c_x  [(size_t)MAX_T * MAX_H];
__device__ uint32_t c_ws1[(size_t)MAX_F * MAX_H];
__device__ uint32_t c_ws3[(size_t)MAX_F * MAX_H];
__device__ uint32_t c_ws2[(size_t)MAX_H * MAX_F];
__device__ uint32_t c_we1[(size_t)MAX_E * MAX_F * MAX_H];
__device__ uint32_t c_we3[(size_t)MAX_E * MAX_F * MAX_H];
__device__ uint32_t c_we2[(size_t)MAX_E * MAX_H * MAX_F];

// ---------------- helpers ----------------
__device__ __forceinline__ uint32_t s2u(const void* p) {
    uint32_t a;
    asm("{ .reg .u64 t; cvta.to.shared.u64 t, %1; cvt.u32.u64 %0, t; }" : "=r"(a) : "l"(p));
    return a;
}
__device__ __forceinline__ uint4 tf32x4(float4 v) {
    uint4 u;
    asm("cvt.rna.tf32.f32 %0, %1;" : "=r"(u.x) : "f"(v.x));
    asm("cvt.rna.tf32.f32 %0, %1;" : "=r"(u.y) : "f"(v.y));
    asm("cvt.rna.tf32.f32 %0, %1;" : "=r"(u.z) : "f"(v.z));
    asm("cvt.rna.tf32.f32 %0, %1;" : "=r"(u.w) : "f"(v.w));
    return u;
}
__device__ __forceinline__ uint32_t tf32_1(float v) {
    uint32_t u;
    asm("cvt.rna.tf32.f32 %0, %1;" : "=r"(u) : "f"(v));
    return u;
}
__device__ __forceinline__ void mma8(float c[4], const uint32_t a[4], const uint32_t b[2]) {
    asm volatile(
        "mma.sync.aligned.m16n8k8.row.col.f32.tf32.tf32.f32 "
        "{%0,%1,%2,%3}, {%4,%5,%6,%7}, {%8,%9}, {%0,%1,%2,%3};"
        : "+f"(c[0]), "+f"(c[1]), "+f"(c[2]), "+f"(c[3])
        : "r"(a[0]), "r"(a[1]), "r"(a[2]), "r"(a[3]), "r"(b[0]), "r"(b[1]));
}
__device__ __forceinline__ void cpa16(uint32_t dst, const uint32_t* src) {
    asm volatile("cp.async.cg.shared.global [%0], [%1], 16;" :: "r"(dst), "l"(src));
}
#define CP_COMMIT() asm volatile("cp.async.commit_group;" ::: "memory")
#define CP_WAIT1()  asm volatile("cp.async.wait_group 1;" ::: "memory")
__device__ __forceinline__ float silu(float x) { return x / (1.f + __expf(-x)); }

// ---------------- kernel: tf32-round a tensor ----------------
__global__ void conv_kernel(const float* __restrict__ in, uint32_t* __restrict__ out, size_t n) {
    size_t i = ((size_t)blockIdx.x * blockDim.x + threadIdx.x) * 4;
    if (i < n) *(uint4*)(out + i) = tf32x4(*(const float4*)(in + i));
}

// ---------------- kernel: zero counters ----------------
__global__ void zero_cnt_kernel() {
    if (threadIdx.x < MAX_E) g_cnt[threadIdx.x] = 0;
}

// ---------------- kernel: gating + top-2 routing ----------------
__global__ void gate_kernel(const float* __restrict__ x,
                            const float* __restrict__ gw,
                            const float* __restrict__ bias,
                            int T, int Hd, int E) {
    int t = blockIdx.x;
    int w = threadIdx.x >> 5, lane = threadIdx.x & 31;
    __shared__ float sc[MAX_E];
    if (w < E) {
        const float* xr = x + (size_t)t * Hd;
        const float* gr = gw + (size_t)w * Hd;
        float s = 0.f;
        for (int i = lane; i < Hd; i += 32) s += xr[i] * gr[i];
        #pragma unroll
        for (int o = 16; o; o >>= 1) s += __shfl_down_sync(0xffffffffu, s, o);
        if (lane == 0) sc[w] = s;
    }
    __syncthreads();
    if (threadIdx.x == 0) {
        float score[MAX_E], rt[MAX_E];
        for (int e = 0; e < E; e++) {
            score[e] = 1.f / (1.f + expf(-sc[e]));
            rt[e] = score[e] + bias[e];
        }
        int b1 = 0;
        for (int e = 1; e < E; e++) if (rt[e] > rt[b1]) b1 = e;
        int b2 = -1;
        for (int e = 0; e < E; e++) {
            if (e == b1) continue;
            if (b2 < 0 || rt[e] > rt[b2]) b2 = e;
        }
        float s1 = score[b1], s2 = score[b2];
        float inv = 1.f / (s1 + s2);
        int p1 = atomicAdd(&g_cnt[b1], 1);
        g_tok[b1 * T + p1] = t; g_gw[b1 * T + p1] = s1 * inv;
        int p2 = atomicAdd(&g_cnt[b2], 1);
        g_tok[b2 * T + p2] = t; g_gw[b2 * T + p2] = s2 * inv;
    }
}

// ---------------- up-projection: dual tf32 mma + fused SwiGLU ----------------
// 128 threads, 4 warps (2x2); warp tile 64x(32+32); block 128x64(dual)x32.
template<bool ROUTED>
__global__ void __launch_bounds__(128, 2)
up_mma(const uint32_t* __restrict__ X, const uint32_t* __restrict__ W1a,
       const uint32_t* __restrict__ W3a, int T, int H, int F)
{
    extern __shared__ __align__(16) uint32_t sm[];
    const int e     = ROUTED ? blockIdx.z : 0;
    const int valid = ROUTED ? g_cnt[e] : T;
    const int row0  = blockIdx.y * BM;
    if (row0 >= valid) return;
    const int col0  = blockIdx.x * 64;
    const int tid   = threadIdx.x, lane = tid & 31, wid = tid >> 5;
    const int wm    = wid >> 1, wn = wid & 1, grp = lane >> 2, tig = lane & 3;
    const uint32_t sb = s2u(sm);

    int* stok = (int*)(sm + 3 * UP_STAGE_U);
    if (ROUTED) {
        int i = row0 + tid; if (i >= valid) i = valid - 1;
        stok[tid] = g_tok[e * T + i];
    }
    __syncthreads();

    const uint32_t* W1 = W1a + (size_t)e * F * H;
    const uint32_t* W3 = W3a + (size_t)e * F * H;
    uint32_t* ACT = ROUTED ? (g_act_e + (size_t)e * T * F) : g_act_s;

    // cp.async mapping: 128 threads; 16B each; A rows r16+16i (i<8), B rows r16+16i (i<4)
    const int r16 = tid >> 3, c4 = tid & 7;
    int atok[8];
    #pragma unroll
    for (int i = 0; i < 8; i++) {
        int r = r16 + 16 * i;
        atok[i] = ROUTED ? stok[r] : (row0 + r);
    }
    const uint32_t* b1base = W1 + (size_t)(col0 + r16) * H + c4 * 4;
    const uint32_t* b3base = W3 + (size_t)(col0 + r16) * H + c4 * 4;
    const uint32_t aoff0 = (uint32_t)(r16 * SA + c4 * 4) * 4;   // bytes
    const uint32_t rstep = 16u * SA * 4u;                        // 16 rows

    const int nch = H / BK;
    auto load_stage = [&](int c) {
        uint32_t dbase = sb + (uint32_t)(c % 3) * UP_STAGE_B;
        int k0 = c * BK;
        #pragma unroll
        for (int i = 0; i < 8; i++)
            cpa16(dbase + aoff0 + i * rstep, X + (size_t)atok[i] * H + k0 + c4 * 4);
        #pragma unroll
        for (int i = 0; i < 4; i++) {
            cpa16(dbase + A_BYTES + aoff0 + i * rstep, b1base + (size_t)(16 * i) * H + k0);
            cpa16(dbase + A_BYTES + B64_U * 4 + aoff0 + i * rstep, b3base + (size_t)(16 * i) * H + k0);
        }
    };

    float acc1[4][4][4] = {}, acc3[4][4][4] = {};

    load_stage(0); CP_COMMIT();
    load_stage(1); CP_COMMIT();

    for (int c = 0; c < nch; ++c) {
        CP_WAIT1();
        __syncthreads();
        if (c + 2 < nch) load_stage(c + 2);
        CP_COMMIT();

        const uint32_t* As  = sm + (c % 3) * UP_STAGE_U;
        const uint32_t* B1s = As + A_TILE_U;
        const uint32_t* B3s = As + A_TILE_U + B64_U;
        #pragma unroll
        for (int j = 0; j < 4; j++) {
            uint32_t af[4][4];
            #pragma unroll
            for (int mt = 0; mt < 4; mt++) {
                const uint32_t* p = As + (wm * 64 + mt * 16 + grp) * SA + 8 * j + tig;
                af[mt][0] = p[0]; af[mt][1] = p[8 * SA]; af[mt][2] = p[4]; af[mt][3] = p[8 * SA + 4];
            }
            #pragma unroll
            for (int nt = 0; nt < 4; nt++) {
                const uint32_t* q1 = B1s + (wn * 32 + nt * 8 + grp) * SA + 8 * j + tig;
                const uint32_t* q3 = B3s + (wn * 32 + nt * 8 + grp) * SA + 8 * j + tig;
                uint32_t bf1[2] = { q1[0], q1[4] };
                uint32_t bf3[2] = { q3[0], q3[4] };
                #pragma unroll
                for (int mt = 0; mt < 4; mt++) {
                    mma8(acc1[mt][nt], af[mt], bf1);
                    mma8(acc3[mt][nt], af[mt], bf3);
                }
            }
        }
    }

    // epilogue: SwiGLU, store tf32-rounded pairs
    #pragma unroll
    for (int mt = 0; mt < 4; mt++) {
        #pragma unroll
        for (int nt = 0; nt < 4; nt++) {
            int cA = col0 + wn * 32 + nt * 8 + 2 * tig;
            #pragma unroll
            for (int half = 0; half < 2; half++) {
                int r = row0 + wm * 64 + mt * 16 + grp + 8 * half;
                if (r >= valid) continue;
                float ox = silu(acc1[mt][nt][2 * half])     * acc3[mt][nt][2 * half];
                float oy = silu(acc1[mt][nt][2 * half + 1]) * acc3[mt][nt][2 * half + 1];
                uint2 u; u.x = tf32_1(ox); u.y = tf32_1(oy);
                *(uint2*)(ACT + (size_t)r * F + cA) = u;
            }
        }
    }
}

// ---------------- down-projection: tf32 mma, plain store or gated scatter ----------------
// 128 threads, 4 warps (2x2); warp tile 64x64; block 128x128x32.
template<bool ROUTED>
__global__ void __launch_bounds__(128, 2)
down_mma(const uint32_t* __restrict__ W2a, float* __restrict__ OUT, int T, int H, int F)
{
    extern __shared__ __align__(16) uint32_t sm[];
    const int e     = ROUTED ? blockIdx.z : 0;
    const int valid = ROUTED ? g_cnt[e] : T;
    const int row0  = blockIdx.y * BM;
    if (row0 >= valid) return;
    const int col0  = blockIdx.x * 128;
    const int tid   = threadIdx.x, lane = tid & 31, wid = tid >> 5;
    const int wm    = wid >> 1, wn = wid & 1, grp = lane >> 2, tig = lane & 3;
    const uint32_t sb = s2u(sm);

    int*   stok = (int*)  (sm + 3 * DN_STAGE_U);
    float* sgw  = (float*)(sm + 3 * DN_STAGE_U + 128);
    if (ROUTED) {
        int i = row0 + tid; if (i >= valid) i = valid - 1;
        stok[tid] = g_tok[e * T + i];
        sgw[tid]  = g_gw [e * T + i];
    }
    __syncthreads();

    const uint32_t* ACT = ROUTED ? (g_act_e + (size_t)e * T * F) : g_act_s;
    const uint32_t* W2  = W2a + (size_t)e * H * F;

    const int r16 = tid >> 3, c4 = tid & 7;
    const uint32_t* abase = ACT + (size_t)(row0 + r16) * F + c4 * 4;  // rows >= valid: stale finite scratch, discarded
    const uint32_t* bbase = W2 + (size_t)(col0 + r16) * F + c4 * 4;
    const uint32_t aoff0 = (uint32_t)(r16 * SA + c4 * 4) * 4;
    const uint32_t rstep = 16u * SA * 4u;

    const int nch = F / BK;
    auto load_stage = [&](int c) {
        uint32_t dbase = sb + (uint32_t)(c % 3) * DN_STAGE_B;
        int k0 = c * BK;
        #pragma unroll
        for (int i = 0; i < 8; i++)
            cpa16(dbase + aoff0 + i * rstep, abase + (size_t)(16 * i) * F + k0);
        #pragma unroll
        for (int i = 0; i < 8; i++)
            cpa16(dbase + A_BYTES + aoff0 + i * rstep, bbase + (size_t)(16 * i) * F + k0);
    };

    float acc[4][8][4] = {};

    load_stage(0); CP_COMMIT();
    load_stage(1); CP_COMMIT();

    for (int c = 0; c < nch; ++c) {
        CP_WAIT1();
        __syncthreads();
        if (c + 2 < nch) load_stage(c + 2);
        CP_COMMIT();

        const uint32_t* As = sm + (c % 3) * DN_STAGE_U;
        const uint32_t* Bs = As + A_TILE_U;
        #pragma unroll
        for (int j = 0; j < 4; j++) {
            uint32_t af[4][4];
            #pragma unroll
            for (int mt = 0; mt < 4; mt++) {
                const uint32_t* p = As + (wm * 64 + mt * 16 + grp) * SA + 8 * j + tig;
                af[mt][0] = p[0]; af[mt][1] = p[8 * SA]; af[mt][2] = p[4]; af[mt][3] = p[8 * SA + 4];
            }
            #pragma unroll
            for (int nt = 0; nt < 8; nt++) {
                const uint32_t* q = Bs + (wn * 64 + nt * 8 + grp) * SA + 8 * j + tig;
                uint32_t bf[2] = { q[0], q[4] };
                #pragma unroll
                for (int mt = 0; mt < 4; mt++) mma8(acc[mt][nt], af[mt], bf);
            }
        }
    }

    #pragma unroll
    for (int mt = 0; mt < 4; mt++) {
        #pragma unroll
        for (int nt = 0; nt < 8; nt++) {
            int cA = col0 + wn * 64 + nt * 8 + 2 * tig;
            #pragma unroll
            for (int half = 0; half < 2; half++) {
                int rloc = wm * 64 + mt * 16 + grp + 8 * half;
                int r = row0 + rloc;
                if (r >= valid) continue;
                float v0 = acc[mt][nt][2 * half], v1 = acc[mt][nt][2 * half + 1];
                if (!ROUTED) {
                    float2 o; o.x = v0; o.y = v1;
                    *(float2*)(OUT + (size_t)r * H + cA) = o;
                } else {
                    int tok = stok[rloc]; float g = sgw[rloc];
                    float* dst = OUT + (size_t)tok * H + cA;
                    atomicAdd(dst,     g * v0);
                    atomicAdd(dst + 1, g * v1);
                }
            }
        }
    }
}

// ---------------- launch ----------------
extern "C" void kernel_launch(void* const* d_in, const int* in_sizes, int n_in,
                              void* d_out, int out_size) {
    const float* x    = (const float*)d_in[0];
    const float* gw   = (const float*)d_in[1];
    const float* bias = (const float*)d_in[2];
    const float* ws1  = (const float*)d_in[3];
    const float* ws2  = (const float*)d_in[4];
    const float* ws3  = (const float*)d_in[5];
    const float* we1  = (const float*)d_in[6];
    const float* we2  = (const float*)d_in[7];
    const float* we3  = (const float*)d_in[8];
    float* out = (float*)d_out;

    const int E  = in_sizes[2];
    const int Hd = in_sizes[1] / E;
    const int F  = in_sizes[3] / Hd;
    const int T  = in_sizes[0] / Hd;

    cudaFuncSetAttribute(up_mma<false>,   cudaFuncAttributeMaxDynamicSharedMemorySize, UP_SMEM);
    cudaFuncSetAttribute(up_mma<true>,    cudaFuncAttributeMaxDynamicSharedMemorySize, UP_SMEM);
    cudaFuncSetAttribute(down_mma<false>, cudaFuncAttributeMaxDynamicSharedMemorySize, DN_SMEM);
    cudaFuncSetAttribute(down_mma<true>,  cudaFuncAttributeMaxDynamicSharedMemorySize, DN_SMEM);

    uint32_t *p_cx, *p_cws1, *p_cws3, *p_cws2, *p_cwe1, *p_cwe3, *p_cwe2;
    cudaGetSymbolAddress((void**)&p_cx,   c_x);
    cudaGetSymbolAddress((void**)&p_cws1, c_ws1);
    cudaGetSymbolAddress((void**)&p_cws3, c_ws3);
    cudaGetSymbolAddress((void**)&p_cws2, c_ws2);
    cudaGetSymbolAddress((void**)&p_cwe1, c_we1);
    cudaGetSymbolAddress((void**)&p_cwe3, c_we3);
    cudaGetSymbolAddress((void**)&p_cwe2, c_we2);

    zero_cnt_kernel<<<1, 32>>>();
    gate_kernel<<<T, 256>>>(x, gw, bias, T, Hd, E);

    auto conv = [&](const float* in, uint32_t* o, size_t n) {
        conv_kernel<<<(unsigned)((n / 4 + 255) / 256), 256>>>(in, o, n);
    };
    conv(x,   p_cx,   (size_t)T * Hd);
    conv(ws1, p_cws1, (size_t)F * Hd);
    conv(ws3, p_cws3, (size_t)F * Hd);
    conv(ws2, p_cws2, (size_t)Hd * F);
    conv(we1, p_cwe1, (size_t)E * F * Hd);
    conv(we3, p_cwe3, (size_t)E * F * Hd);
    conv(we2, p_cwe2, (size_t)E * Hd * F);

    dim3 blk(128);
    up_mma<false><<<dim3(F / 64, T / BM), blk, UP_SMEM>>>(p_cx, p_cws1, p_cws3, T, Hd, F);
    down_mma<false><<<dim3(Hd / 128, T / BM), blk, DN_SMEM>>>(p_cws2, out, T, Hd, F);
    up_mma<true><<<dim3(F / 64, T / BM, E), blk, UP_SMEM>>>(p_cx, p_cwe1, p_cwe3, T, Hd, F);
    down_mma<true><<<dim3(Hd / 128, T / BM, E), blk, DN_SMEM>>>(p_cwe2, out, T, Hd, F);
}

// round 9
// speedup vs baseline: 3.8385x; 1.0093x over previous
#include <cuda_runtime.h>
#include <math.h>
#include <stdint.h>

// Shapes fixed by dataset: T=4096, H=2048, F=1408, E=8, K=2
constexpr int MAX_E = 8;
constexpr int MAX_T = 4096;
constexpr int MAX_F = 1408;
constexpr int MAX_H = 2048;

constexpr int BM = 128, BK = 32;
constexpr int SA = 36;                       // padded smem row stride (words)
constexpr uint32_t A_TILE_U  = 128 * SA;
constexpr uint32_t B64_U     = 64 * SA;
constexpr uint32_t B128_U    = 128 * SA;
constexpr uint32_t A_BYTES   = A_TILE_U * 4;
constexpr uint32_t UP_STAGE_U = A_TILE_U + 2 * B64_U;
constexpr uint32_t DN_STAGE_U = A_TILE_U + B128_U;
constexpr uint32_t UP_STAGE_B = UP_STAGE_U * 4;
constexpr uint32_t DN_STAGE_B = DN_STAGE_U * 4;
constexpr uint32_t UP_SMEM = 3 * UP_STAGE_B + 512;      // 111104 -> 2 CTAs/SM
constexpr uint32_t DN_SMEM = 3 * DN_STAGE_B + 1024;     // 111616 -> 2 CTAs/SM

// ---------------- scratch (static; no allocations allowed) ----------------
__device__ int      g_cnt[MAX_E];
__device__ int      g_tok[MAX_E * MAX_T];
__device__ float    g_gw [MAX_E * MAX_T];
__device__ uint32_t g_act_s[(size_t)MAX_T * MAX_F];
__device__ uint32_t g_act_e[(size_t)MAX_E * MAX_T * MAX_F];
__device__ uint32_t c_x  [(size_t)MAX_T * MAX_H];
__device__ uint32_t c_ws1[(size_t)MAX_F * MAX_H];
__device__ uint32_t c_ws3[(size_t)MAX_F * MAX_H];
__device__ uint32_t c_ws2[(size_t)MAX_H * MAX_F];
__device__ uint32_t c_we1[(size_t)MAX_E * MAX_F * MAX_H];
__device__ uint32_t c_we3[(size_t)MAX_E * MAX_F * MAX_H];
__device__ uint32_t c_we2[(size_t)MAX_E * MAX_H * MAX_F];

// ---------------- helpers ----------------
__device__ __forceinline__ uint32_t s2u(const void* p) {
    uint32_t a;
    asm("{ .reg .u64 t; cvta.to.shared.u64 t, %1; cvt.u32.u64 %0, t; }" : "=r"(a) : "l"(p));
    return a;
}
__device__ __forceinline__ uint4 tf32x4(float4 v) {
    uint4 u;
    asm("cvt.rna.tf32.f32 %0, %1;" : "=r"(u.x) : "f"(v.x));
    asm("cvt.rna.tf32.f32 %0, %1;" : "=r"(u.y) : "f"(v.y));
    asm("cvt.rna.tf32.f32 %0, %1;" : "=r"(u.z) : "f"(v.z));
    asm("cvt.rna.tf32.f32 %0, %1;" : "=r"(u.w) : "f"(v.w));
    return u;
}
__device__ __forceinline__ uint32_t tf32_1(float v) {
    uint32_t u;
    asm("cvt.rna.tf32.f32 %0, %1;" : "=r"(u) : "f"(v));
    return u;
}
__device__ __forceinline__ void mma8(float c[4], const uint32_t a[4], const uint32_t b[2]) {
    asm volatile(
        "mma.sync.aligned.m16n8k8.row.col.f32.tf32.tf32.f32 "
        "{%0,%1,%2,%3}, {%4,%5,%6,%7}, {%8,%9}, {%0,%1,%2,%3};"
        : "+f"(c[0]), "+f"(c[1]), "+f"(c[2]), "+f"(c[3])
        : "r"(a[0]), "r"(a[1]), "r"(a[2]), "r"(a[3]), "r"(b[0]), "r"(b[1]));
}
#define LDSM4(r, a) asm volatile( \
    "ldmatrix.sync.aligned.m8n8.x4.shared.b16 {%0,%1,%2,%3}, [%4];" \
    : "=r"((r)[0]), "=r"((r)[1]), "=r"((r)[2]), "=r"((r)[3]) : "r"(a))
__device__ __forceinline__ void cpa16(uint32_t dst, const uint32_t* src) {
    asm volatile("cp.async.cg.shared.global [%0], [%1], 16;" :: "r"(dst), "l"(src));
}
#define CP_COMMIT() asm volatile("cp.async.commit_group;" ::: "memory")
#define CP_WAIT1()  asm volatile("cp.async.wait_group 1;" ::: "memory")
__device__ __forceinline__ float silu(float x) { return x / (1.f + __expf(-x)); }

// ---------------- kernel: tf32-round a tensor ----------------
__global__ void conv_kernel(const float* __restrict__ in, uint32_t* __restrict__ out, size_t n) {
    size_t i = ((size_t)blockIdx.x * blockDim.x + threadIdx.x) * 4;
    if (i < n) *(uint4*)(out + i) = tf32x4(*(const float4*)(in + i));
}

// ---------------- kernel: zero counters ----------------
__global__ void zero_cnt_kernel() {
    if (threadIdx.x < MAX_E) g_cnt[threadIdx.x] = 0;
}

// ---------------- kernel: gating + top-2 routing ----------------
__global__ void gate_kernel(const float* __restrict__ x,
                            const float* __restrict__ gw,
                            const float* __restrict__ bias,
                            int T, int Hd, int E) {
    int t = blockIdx.x;
    int w = threadIdx.x >> 5, lane = threadIdx.x & 31;
    __shared__ float sc[MAX_E];
    if (w < E) {
        const float* xr = x + (size_t)t * Hd;
        const float* gr = gw + (size_t)w * Hd;
        float s = 0.f;
        for (int i = lane; i < Hd; i += 32) s += xr[i] * gr[i];
        #pragma unroll
        for (int o = 16; o; o >>= 1) s += __shfl_down_sync(0xffffffffu, s, o);
        if (lane == 0) sc[w] = s;
    }
    __syncthreads();
    if (threadIdx.x == 0) {
        float score[MAX_E], rt[MAX_E];
        for (int e = 0; e < E; e++) {
            score[e] = 1.f / (1.f + expf(-sc[e]));
            rt[e] = score[e] + bias[e];
        }
        int b1 = 0;
        for (int e = 1; e < E; e++) if (rt[e] > rt[b1]) b1 = e;
        int b2 = -1;
        for (int e = 0; e < E; e++) {
            if (e == b1) continue;
            if (b2 < 0 || rt[e] > rt[b2]) b2 = e;
        }
        float s1 = score[b1], s2 = score[b2];
        float inv = 1.f / (s1 + s2);
        int p1 = atomicAdd(&g_cnt[b1], 1);
        g_tok[b1 * T + p1] = t; g_gw[b1 * T + p1] = s1 * inv;
        int p2 = atomicAdd(&g_cnt[b2], 1);
        g_tok[b2 * T + p2] = t; g_gw[b2 * T + p2] = s2 * inv;
    }
}

// ---------------- up-projection: dual tf32 mma + fused SwiGLU ----------------
// 128 threads, 4 warps (2x2); warp tile 64x(32+32); block 128x64(dual)x32.
template<bool ROUTED>
__global__ void __launch_bounds__(128, 2)
up_mma(const uint32_t* __restrict__ X, const uint32_t* __restrict__ W1a,
       const uint32_t* __restrict__ W3a, int T, int H, int F)
{
    extern __shared__ __align__(16) uint32_t sm[];
    const int e     = ROUTED ? blockIdx.z : 0;
    const int valid = ROUTED ? g_cnt[e] : T;
    const int row0  = blockIdx.y * BM;
    if (row0 >= valid) return;
    const int col0  = blockIdx.x * 64;
    const int tid   = threadIdx.x, lane = tid & 31, wid = tid >> 5;
    const int wm    = wid >> 1, wn = wid & 1, grp = lane >> 2, tig = lane & 3;
    const uint32_t sb = s2u(sm);

    int* stok = (int*)(sm + 3 * UP_STAGE_U);
    if (ROUTED) {
        int i = row0 + tid; if (i >= valid) i = valid - 1;
        stok[tid] = g_tok[e * T + i];
    }
    __syncthreads();

    const uint32_t* W1 = W1a + (size_t)e * F * H;
    const uint32_t* W3 = W3a + (size_t)e * F * H;
    uint32_t* ACT = ROUTED ? (g_act_e + (size_t)e * T * F) : g_act_s;

    // cp.async mapping
    const int r16 = tid >> 3, c4 = tid & 7;
    int atok[8];
    #pragma unroll
    for (int i = 0; i < 8; i++) {
        int r = r16 + 16 * i;
        atok[i] = ROUTED ? stok[r] : (row0 + r);
    }
    const uint32_t* b1base = W1 + (size_t)(col0 + r16) * H + c4 * 4;
    const uint32_t* b3base = W3 + (size_t)(col0 + r16) * H + c4 * 4;
    const uint32_t aoff0 = (uint32_t)(r16 * SA + c4 * 4) * 4;
    const uint32_t rstep = 16u * SA * 4u;

    // ldmatrix addresses (byte offsets within a stage)
    const int lrow = lane & 7;
    uint32_t aAddr[4];
    #pragma unroll
    for (int mt = 0; mt < 4; mt++) {
        int row = wm * 64 + mt * 16 + lrow + 8 * ((lane >> 3) & 1);
        aAddr[mt] = sb + (uint32_t)(row * SA + 4 * (lane >> 4)) * 4;
    }
    uint32_t b1Addr[2], b3Addr[2];
    #pragma unroll
    for (int p = 0; p < 2; p++) {
        int row = wn * 32 + p * 16 + lrow + 8 * (lane >> 4);
        uint32_t off = (uint32_t)(row * SA + 4 * ((lane >> 3) & 1)) * 4;
        b1Addr[p] = sb + A_BYTES + off;
        b3Addr[p] = sb + A_BYTES + B64_U * 4 + off;
    }

    const int nch = H / BK;
    auto load_stage = [&](int c) {
        uint32_t dbase = sb + (uint32_t)(c % 3) * UP_STAGE_B;
        int k0 = c * BK;
        #pragma unroll
        for (int i = 0; i < 8; i++)
            cpa16(dbase + aoff0 + i * rstep, X + (size_t)atok[i] * H + k0 + c4 * 4);
        #pragma unroll
        for (int i = 0; i < 4; i++) {
            cpa16(dbase + A_BYTES + aoff0 + i * rstep, b1base + (size_t)(16 * i) * H + k0);
            cpa16(dbase + A_BYTES + B64_U * 4 + aoff0 + i * rstep, b3base + (size_t)(16 * i) * H + k0);
        }
    };

    float acc1[4][4][4] = {}, acc3[4][4][4] = {};

    load_stage(0); CP_COMMIT();
    load_stage(1); CP_COMMIT();

    for (int c = 0; c < nch; ++c) {
        CP_WAIT1();
        __syncthreads();
        if (c + 2 < nch) load_stage(c + 2);
        CP_COMMIT();

        const uint32_t stof = (uint32_t)(c % 3) * UP_STAGE_B;
        #pragma unroll
        for (int j = 0; j < 4; j++) {
            uint32_t af[4][4];
            #pragma unroll
            for (int mt = 0; mt < 4; mt++) LDSM4(af[mt], aAddr[mt] + stof + 32u * j);
            uint32_t bf1[2][4], bf3[2][4];
            #pragma unroll
            for (int p = 0; p < 2; p++) {
                LDSM4(bf1[p], b1Addr[p] + stof + 32u * j);
                LDSM4(bf3[p], b3Addr[p] + stof + 32u * j);
            }
            #pragma unroll
            for (int nt = 0; nt < 4; nt++) {
                const int pp = nt >> 1, q = nt & 1;
                uint32_t x1[2] = { bf1[pp][2 * q], bf1[pp][2 * q + 1] };
                uint32_t x3[2] = { bf3[pp][2 * q], bf3[pp][2 * q + 1] };
                #pragma unroll
                for (int mt = 0; mt < 4; mt++) {
                    mma8(acc1[mt][nt], af[mt], x1);
                    mma8(acc3[mt][nt], af[mt], x3);
                }
            }
        }
    }

    // epilogue: SwiGLU, store tf32-rounded pairs
    #pragma unroll
    for (int mt = 0; mt < 4; mt++) {
        #pragma unroll
        for (int nt = 0; nt < 4; nt++) {
            int cA = col0 + wn * 32 + nt * 8 + 2 * tig;
            #pragma unroll
            for (int half = 0; half < 2; half++) {
                int r = row0 + wm * 64 + mt * 16 + grp + 8 * half;
                if (r >= valid) continue;
                float ox = silu(acc1[mt][nt][2 * half])     * acc3[mt][nt][2 * half];
                float oy = silu(acc1[mt][nt][2 * half + 1]) * acc3[mt][nt][2 * half + 1];
                uint2 u; u.x = tf32_1(ox); u.y = tf32_1(oy);
                *(uint2*)(ACT + (size_t)r * F + cA) = u;
            }
        }
    }
}

// ---------------- down-projection: tf32 mma, plain store or gated scatter ----------------
// 128 threads, 4 warps (2x2); warp tile 64x64; block 128x128x32.
template<bool ROUTED>
__global__ void __launch_bounds__(128, 2)
down_mma(const uint32_t* __restrict__ W2a, float* __restrict__ OUT, int T, int H, int F)
{
    extern __shared__ __align__(16) uint32_t sm[];
    const int e     = ROUTED ? blockIdx.z : 0;
    const int valid = ROUTED ? g_cnt[e] : T;
    const int row0  = blockIdx.y * BM;
    if (row0 >= valid) return;
    const int col0  = blockIdx.x * 128;
    const int tid   = threadIdx.x, lane = tid & 31, wid = tid >> 5;
    const int wm    = wid >> 1, wn = wid & 1, grp = lane >> 2, tig = lane & 3;
    const uint32_t sb = s2u(sm);

    int*   stok = (int*)  (sm + 3 * DN_STAGE_U);
    float* sgw  = (float*)(sm + 3 * DN_STAGE_U + 128);
    if (ROUTED) {
        int i = row0 + tid; if (i >= valid) i = valid - 1;
        stok[tid] = g_tok[e * T + i];
        sgw[tid]  = g_gw [e * T + i];
    }
    __syncthreads();

    const uint32_t* ACT = ROUTED ? (g_act_e + (size_t)e * T * F) : g_act_s;
    const uint32_t* W2  = W2a + (size_t)e * H * F;

    const int r16 = tid >> 3, c4 = tid & 7;
    const uint32_t* abase = ACT + (size_t)(row0 + r16) * F + c4 * 4;  // rows >= valid: stale finite scratch, discarded
    const uint32_t* bbase = W2 + (size_t)(col0 + r16) * F + c4 * 4;
    const uint32_t aoff0 = (uint32_t)(r16 * SA + c4 * 4) * 4;
    const uint32_t rstep = 16u * SA * 4u;

    // ldmatrix addresses
    const int lrow = lane & 7;
    uint32_t aAddr[4];
    #pragma unroll
    for (int mt = 0; mt < 4; mt++) {
        int row = wm * 64 + mt * 16 + lrow + 8 * ((lane >> 3) & 1);
        aAddr[mt] = sb + (uint32_t)(row * SA + 4 * (lane >> 4)) * 4;
    }
    uint32_t bAddr[4];
    #pragma unroll
    for (int p = 0; p < 4; p++) {
        int row = wn * 64 + p * 16 + lrow + 8 * (lane >> 4);
        bAddr[p] = sb + A_BYTES + (uint32_t)(row * SA + 4 * ((lane >> 3) & 1)) * 4;
    }

    const int nch = F / BK;
    auto load_stage = [&](int c) {
        uint32_t dbase = sb + (uint32_t)(c % 3) * DN_STAGE_B;
        int k0 = c * BK;
        #pragma unroll
        for (int i = 0; i < 8; i++)
            cpa16(dbase + aoff0 + i * rstep, abase + (size_t)(16 * i) * F + k0);
        #pragma unroll
        for (int i = 0; i < 8; i++)
            cpa16(dbase + A_BYTES + aoff0 + i * rstep, bbase + (size_t)(16 * i) * F + k0);
    };

    float acc[4][8][4] = {};

    load_stage(0); CP_COMMIT();
    load_stage(1); CP_COMMIT();

    for (int c = 0; c < nch; ++c) {
        CP_WAIT1();
        __syncthreads();
        if (c + 2 < nch) load_stage(c + 2);
        CP_COMMIT();

        const uint32_t stof = (uint32_t)(c % 3) * DN_STAGE_B;
        #pragma unroll
        for (int j = 0; j < 4; j++) {
            uint32_t af[4][4];
            #pragma unroll
            for (int mt = 0; mt < 4; mt++) LDSM4(af[mt], aAddr[mt] + stof + 32u * j);
            uint32_t bf[4][4];
            #pragma unroll
            for (int p = 0; p < 4; p++) LDSM4(bf[p], bAddr[p] + stof + 32u * j);
            #pragma unroll
            for (int nt = 0; nt < 8; nt++) {
                const int pp = nt >> 1, q = nt & 1;
                uint32_t xb[2] = { bf[pp][2 * q], bf[pp][2 * q + 1] };
                #pragma unroll
                for (int mt = 0; mt < 4; mt++) mma8(acc[mt][nt], af[mt], xb);
            }
        }
    }

    #pragma unroll
    for (int mt = 0; mt < 4; mt++) {
        #pragma unroll
        for (int nt = 0; nt < 8; nt++) {
            int cA = col0 + wn * 64 + nt * 8 + 2 * tig;
            #pragma unroll
            for (int half = 0; half < 2; half++) {
                int rloc = wm * 64 + mt * 16 + grp + 8 * half;
                int r = row0 + rloc;
                if (r >= valid) continue;
                float v0 = acc[mt][nt][2 * half], v1 = acc[mt][nt][2 * half + 1];
                if (!ROUTED) {
                    float2 o; o.x = v0; o.y = v1;
                    *(float2*)(OUT + (size_t)r * H + cA) = o;
                } else {
                    int tok = stok[rloc]; float g = sgw[rloc];
                    float* dst = OUT + (size_t)tok * H + cA;
                    atomicAdd(dst,     g * v0);
                    atomicAdd(dst + 1, g * v1);
                }
            }
        }
    }
}

// ---------------- launch ----------------
extern "C" void kernel_launch(void* const* d_in, const int* in_sizes, int n_in,
                              void* d_out, int out_size) {
    const float* x    = (const float*)d_in[0];
    const float* gw   = (const float*)d_in[1];
    const float* bias = (const float*)d_in[2];
    const float* ws1  = (const float*)d_in[3];
    const float* ws2  = (const float*)d_in[4];
    const float* ws3  = (const float*)d_in[5];
    const float* we1  = (const float*)d_in[6];
    const float* we2  = (const float*)d_in[7];
    const float* we3  = (const float*)d_in[8];
    float* out = (float*)d_out;

    const int E  = in_sizes[2];
    const int Hd = in_sizes[1] / E;
    const int F  = in_sizes[3] / Hd;
    const int T  = in_sizes[0] / Hd;

    cudaFuncSetAttribute(up_mma<false>,   cudaFuncAttributeMaxDynamicSharedMemorySize, UP_SMEM);
    cudaFuncSetAttribute(up_mma<true>,    cudaFuncAttributeMaxDynamicSharedMemorySize, UP_SMEM);
    cudaFuncSetAttribute(down_mma<false>, cudaFuncAttributeMaxDynamicSharedMemorySize, DN_SMEM);
    cudaFuncSetAttribute(down_mma<true>,  cudaFuncAttributeMaxDynamicSharedMemorySize, DN_SMEM);

    uint32_t *p_cx, *p_cws1, *p_cws3, *p_cws2, *p_cwe1, *p_cwe3, *p_cwe2;
    cudaGetSymbolAddress((void**)&p_cx,   c_x);
    cudaGetSymbolAddress((void**)&p_cws1, c_ws1);
    cudaGetSymbolAddress((void**)&p_cws3, c_ws3);
    cudaGetSymbolAddress((void**)&p_cws2, c_ws2);
    cudaGetSymbolAddress((void**)&p_cwe1, c_we1);
    cudaGetSymbolAddress((void**)&p_cwe3, c_we3);
    cudaGetSymbolAddress((void**)&p_cwe2, c_we2);

    zero_cnt_kernel<<<1, 32>>>();
    gate_kernel<<<T, 256>>>(x, gw, bias, T, Hd, E);

    auto conv = [&](const float* in, uint32_t* o, size_t n) {
        conv_kernel<<<(unsigned)((n / 4 + 255) / 256), 256>>>(in, o, n);
    };
    conv(x,   p_cx,   (size_t)T * Hd);
    conv(ws1, p_cws1, (size_t)F * Hd);
    conv(ws3, p_cws3, (size_t)F * Hd);
    conv(ws2, p_cws2, (size_t)Hd * F);
    conv(we1, p_cwe1, (size_t)E * F * Hd);
    conv(we3, p_cwe3, (size_t)E * F * Hd);
    conv(we2, p_cwe2, (size_t)E * Hd * F);

    dim3 blk(128);
    up_mma<false><<<dim3(F / 64, T / BM), blk, UP_SMEM>>>(p_cx, p_cws1, p_cws3, T, Hd, F);
    down_mma<false><<<dim3(Hd / 128, T / BM), blk, DN_SMEM>>>(p_cws2, out, T, Hd, F);
    up_mma<true><<<dim3(F / 64, T / BM, E), blk, UP_SMEM>>>(p_cx, p_cwe1, p_cwe3, T, Hd, F);
    down_mma<true><<<dim3(Hd / 128, T / BM, E), blk, DN_SMEM>>>(p_cwe2, out, T, Hd, F);
}

// round 10
// speedup vs baseline: 4.2502x; 1.1072x over previous
#include <cuda_runtime.h>
#include <math.h>
#include <stdint.h>

// Shapes fixed by dataset: T=4096, H=2048, F=1408, E=8, K=2
constexpr int MAX_E = 8;
constexpr int MAX_T = 4096;
constexpr int MAX_F = 1408;
constexpr int MAX_H = 2048;

constexpr int BM = 128, BK = 32;
constexpr int SA = 36;                       // padded smem row stride (words)
constexpr uint32_t A_TILE_U  = 128 * SA;
constexpr uint32_t B64_U     = 64 * SA;
constexpr uint32_t B128_U    = 128 * SA;
constexpr uint32_t A_BYTES   = A_TILE_U * 4;
constexpr uint32_t UP_STAGE_U = A_TILE_U + 2 * B64_U;
constexpr uint32_t DN_STAGE_U = A_TILE_U + B128_U;
constexpr uint32_t UP_STAGE_B = UP_STAGE_U * 4;
constexpr uint32_t DN_STAGE_B = DN_STAGE_U * 4;
constexpr uint32_t UP_SMEM = 3 * UP_STAGE_B + 512;      // 111104 -> 2 CTAs/SM
constexpr uint32_t DN_SMEM = 3 * DN_STAGE_B + 1024;     // 111616 -> 2 CTAs/SM

// ---------------- scratch (static; no allocations allowed) ----------------
__device__ int      g_cnt[MAX_E];
__device__ int      g_tok[MAX_E * MAX_T];
__device__ float    g_gw [MAX_E * MAX_T];
__device__ uint32_t g_act_s[(size_t)MAX_T * MAX_F];
__device__ uint32_t g_act_e[(size_t)MAX_E * MAX_T * MAX_F];
__device__ float    g_routed[(size_t)MAX_T * MAX_H];   // routed-expert accumulator
__device__ uint32_t c_x  [(size_t)MAX_T * MAX_H];
__device__ uint32_t c_ws1[(size_t)MAX_F * MAX_H];
__device__ uint32_t c_ws3[(size_t)MAX_F * MAX_H];
__device__ uint32_t c_ws2[(size_t)MAX_H * MAX_F];
__device__ uint32_t c_we1[(size_t)MAX_E * MAX_F * MAX_H];
__device__ uint32_t c_we3[(size_t)MAX_E * MAX_F * MAX_H];
__device__ uint32_t c_we2[(size_t)MAX_E * MAX_H * MAX_F];

// ---------------- helpers ----------------
__device__ __forceinline__ uint32_t s2u(const void* p) {
    uint32_t a;
    asm("{ .reg .u64 t; cvta.to.shared.u64 t, %1; cvt.u32.u64 %0, t; }" : "=r"(a) : "l"(p));
    return a;
}
__device__ __forceinline__ uint4 tf32x4(float4 v) {
    uint4 u;
    asm("cvt.rna.tf32.f32 %0, %1;" : "=r"(u.x) : "f"(v.x));
    asm("cvt.rna.tf32.f32 %0, %1;" : "=r"(u.y) : "f"(v.y));
    asm("cvt.rna.tf32.f32 %0, %1;" : "=r"(u.z) : "f"(v.z));
    asm("cvt.rna.tf32.f32 %0, %1;" : "=r"(u.w) : "f"(v.w));
    return u;
}
__device__ __forceinline__ uint32_t tf32_1(float v) {
    uint32_t u;
    asm("cvt.rna.tf32.f32 %0, %1;" : "=r"(u) : "f"(v));
    return u;
}
__device__ __forceinline__ void mma8(float c[4], const uint32_t a[4], const uint32_t b[2]) {
    asm volatile(
        "mma.sync.aligned.m16n8k8.row.col.f32.tf32.tf32.f32 "
        "{%0,%1,%2,%3}, {%4,%5,%6,%7}, {%8,%9}, {%0,%1,%2,%3};"
        : "+f"(c[0]), "+f"(c[1]), "+f"(c[2]), "+f"(c[3])
        : "r"(a[0]), "r"(a[1]), "r"(a[2]), "r"(a[3]), "r"(b[0]), "r"(b[1]));
}
#define LDSM4(r, a) asm volatile( \
    "ldmatrix.sync.aligned.m8n8.x4.shared.b16 {%0,%1,%2,%3}, [%4];" \
    : "=r"((r)[0]), "=r"((r)[1]), "=r"((r)[2]), "=r"((r)[3]) : "r"(a))
__device__ __forceinline__ void cpa16(uint32_t dst, const uint32_t* src) {
    asm volatile("cp.async.cg.shared.global [%0], [%1], 16;" :: "r"(dst), "l"(src));
}
#define CP_COMMIT() asm volatile("cp.async.commit_group;" ::: "memory")
#define CP_WAIT1()  asm volatile("cp.async.wait_group 1;" ::: "memory")
__device__ __forceinline__ float silu(float x) { return x / (1.f + __expf(-x)); }

// ---------------- kernel: tf32-round a tensor ----------------
__global__ void conv_kernel(const float* __restrict__ in, uint32_t* __restrict__ out, size_t n) {
    size_t i = ((size_t)blockIdx.x * blockDim.x + threadIdx.x) * 4;
    if (i < n) *(uint4*)(out + i) = tf32x4(*(const float4*)(in + i));
}

// ---------------- kernel: zero counters ----------------
__global__ void zero_cnt_kernel() {
    if (threadIdx.x < MAX_E) g_cnt[threadIdx.x] = 0;
}

// ---------------- kernel: zero routed accumulator ----------------
__global__ void zero_routed_kernel(size_t n) {
    size_t i = ((size_t)blockIdx.x * blockDim.x + threadIdx.x) * 4;
    if (i < n) {
        float4 z; z.x = 0.f; z.y = 0.f; z.z = 0.f; z.w = 0.f;
        *(float4*)(g_routed + i) = z;
    }
}

// ---------------- kernel: OUT = OUT + routed ----------------
__global__ void final_add_kernel(float* __restrict__ out, size_t n) {
    size_t i = ((size_t)blockIdx.x * blockDim.x + threadIdx.x) * 4;
    if (i < n) {
        float4 a = *(const float4*)(out + i);
        float4 b = *(const float4*)(g_routed + i);
        a.x += b.x; a.y += b.y; a.z += b.z; a.w += b.w;
        *(float4*)(out + i) = a;
    }
}

// ---------------- kernel: gating + top-2 routing ----------------
__global__ void gate_kernel(const float* __restrict__ x,
                            const float* __restrict__ gw,
                            const float* __restrict__ bias,
                            int T, int Hd, int E) {
    int t = blockIdx.x;
    int w = threadIdx.x >> 5, lane = threadIdx.x & 31;
    __shared__ float sc[MAX_E];
    if (w < E) {
        const float* xr = x + (size_t)t * Hd;
        const float* gr = gw + (size_t)w * Hd;
        float s = 0.f;
        for (int i = lane; i < Hd; i += 32) s += xr[i] * gr[i];
        #pragma unroll
        for (int o = 16; o; o >>= 1) s += __shfl_down_sync(0xffffffffu, s, o);
        if (lane == 0) sc[w] = s;
    }
    __syncthreads();
    if (threadIdx.x == 0) {
        float score[MAX_E], rt[MAX_E];
        for (int e = 0; e < E; e++) {
            score[e] = 1.f / (1.f + expf(-sc[e]));
            rt[e] = score[e] + bias[e];
        }
        int b1 = 0;
        for (int e = 1; e < E; e++) if (rt[e] > rt[b1]) b1 = e;
        int b2 = -1;
        for (int e = 0; e < E; e++) {
            if (e == b1) continue;
            if (b2 < 0 || rt[e] > rt[b2]) b2 = e;
        }
        float s1 = score[b1], s2 = score[b2];
        float inv = 1.f / (s1 + s2);
        int p1 = atomicAdd(&g_cnt[b1], 1);
        g_tok[b1 * T + p1] = t; g_gw[b1 * T + p1] = s1 * inv;
        int p2 = atomicAdd(&g_cnt[b2], 1);
        g_tok[b2 * T + p2] = t; g_gw[b2 * T + p2] = s2 * inv;
    }
}

// ---------------- up-projection: dual tf32 mma + fused SwiGLU ----------------
template<bool ROUTED>
__global__ void __launch_bounds__(128, 2)
up_mma(const uint32_t* __restrict__ X, const uint32_t* __restrict__ W1a,
       const uint32_t* __restrict__ W3a, int T, int H, int F)
{
    extern __shared__ __align__(16) uint32_t sm[];
    const int e     = ROUTED ? blockIdx.z : 0;
    const int valid = ROUTED ? g_cnt[e] : T;
    const int row0  = blockIdx.y * BM;
    if (row0 >= valid) return;
    const int col0  = blockIdx.x * 64;
    const int tid   = threadIdx.x, lane = tid & 31, wid = tid >> 5;
    const int wm    = wid >> 1, wn = wid & 1, grp = lane >> 2, tig = lane & 3;
    const uint32_t sb = s2u(sm);

    int* stok = (int*)(sm + 3 * UP_STAGE_U);
    if (ROUTED) {
        int i = row0 + tid; if (i >= valid) i = valid - 1;
        stok[tid] = g_tok[e * T + i];
    }
    __syncthreads();

    const uint32_t* W1 = W1a + (size_t)e * F * H;
    const uint32_t* W3 = W3a + (size_t)e * F * H;
    uint32_t* ACT = ROUTED ? (g_act_e + (size_t)e * T * F) : g_act_s;

    const int r16 = tid >> 3, c4 = tid & 7;
    int atok[8];
    #pragma unroll
    for (int i = 0; i < 8; i++) {
        int r = r16 + 16 * i;
        atok[i] = ROUTED ? stok[r] : (row0 + r);
    }
    const uint32_t* b1base = W1 + (size_t)(col0 + r16) * H + c4 * 4;
    const uint32_t* b3base = W3 + (size_t)(col0 + r16) * H + c4 * 4;
    const uint32_t aoff0 = (uint32_t)(r16 * SA + c4 * 4) * 4;
    const uint32_t rstep = 16u * SA * 4u;

    const int lrow = lane & 7;
    uint32_t aAddr[4];
    #pragma unroll
    for (int mt = 0; mt < 4; mt++) {
        int row = wm * 64 + mt * 16 + lrow + 8 * ((lane >> 3) & 1);
        aAddr[mt] = sb + (uint32_t)(row * SA + 4 * (lane >> 4)) * 4;
    }
    uint32_t b1Addr[2], b3Addr[2];
    #pragma unroll
    for (int p = 0; p < 2; p++) {
        int row = wn * 32 + p * 16 + lrow + 8 * (lane >> 4);
        uint32_t off = (uint32_t)(row * SA + 4 * ((lane >> 3) & 1)) * 4;
        b1Addr[p] = sb + A_BYTES + off;
        b3Addr[p] = sb + A_BYTES + B64_U * 4 + off;
    }

    const int nch = H / BK;
    auto load_stage = [&](int c) {
        uint32_t dbase = sb + (uint32_t)(c % 3) * UP_STAGE_B;
        int k0 = c * BK;
        #pragma unroll
        for (int i = 0; i < 8; i++)
            cpa16(dbase + aoff0 + i * rstep, X + (size_t)atok[i] * H + k0 + c4 * 4);
        #pragma unroll
        for (int i = 0; i < 4; i++) {
            cpa16(dbase + A_BYTES + aoff0 + i * rstep, b1base + (size_t)(16 * i) * H + k0);
            cpa16(dbase + A_BYTES + B64_U * 4 + aoff0 + i * rstep, b3base + (size_t)(16 * i) * H + k0);
        }
    };

    float acc1[4][4][4] = {}, acc3[4][4][4] = {};

    load_stage(0); CP_COMMIT();
    load_stage(1); CP_COMMIT();

    for (int c = 0; c < nch; ++c) {
        CP_WAIT1();
        __syncthreads();
        if (c + 2 < nch) load_stage(c + 2);
        CP_COMMIT();

        const uint32_t stof = (uint32_t)(c % 3) * UP_STAGE_B;
        #pragma unroll
        for (int j = 0; j < 4; j++) {
            uint32_t af[4][4];
            #pragma unroll
            for (int mt = 0; mt < 4; mt++) LDSM4(af[mt], aAddr[mt] + stof + 32u * j);
            uint32_t bf1[2][4], bf3[2][4];
            #pragma unroll
            for (int p = 0; p < 2; p++) {
                LDSM4(bf1[p], b1Addr[p] + stof + 32u * j);
                LDSM4(bf3[p], b3Addr[p] + stof + 32u * j);
            }
            #pragma unroll
            for (int nt = 0; nt < 4; nt++) {
                const int pp = nt >> 1, q = nt & 1;
                uint32_t x1[2] = { bf1[pp][2 * q], bf1[pp][2 * q + 1] };
                uint32_t x3[2] = { bf3[pp][2 * q], bf3[pp][2 * q + 1] };
                #pragma unroll
                for (int mt = 0; mt < 4; mt++) {
                    mma8(acc1[mt][nt], af[mt], x1);
                    mma8(acc3[mt][nt], af[mt], x3);
                }
            }
        }
    }

    #pragma unroll
    for (int mt = 0; mt < 4; mt++) {
        #pragma unroll
        for (int nt = 0; nt < 4; nt++) {
            int cA = col0 + wn * 32 + nt * 8 + 2 * tig;
            #pragma unroll
            for (int half = 0; half < 2; half++) {
                int r = row0 + wm * 64 + mt * 16 + grp + 8 * half;
                if (r >= valid) continue;
                float ox = silu(acc1[mt][nt][2 * half])     * acc3[mt][nt][2 * half];
                float oy = silu(acc1[mt][nt][2 * half + 1]) * acc3[mt][nt][2 * half + 1];
                uint2 u; u.x = tf32_1(ox); u.y = tf32_1(oy);
                *(uint2*)(ACT + (size_t)r * F + cA) = u;
            }
        }
    }
}

// ---------------- down-projection: tf32 mma, plain store or gated scatter ----------------
template<bool ROUTED>
__global__ void __launch_bounds__(128, 2)
down_mma(const uint32_t* __restrict__ W2a, float* __restrict__ OUT, int T, int H, int F)
{
    extern __shared__ __align__(16) uint32_t sm[];
    const int e     = ROUTED ? blockIdx.z : 0;
    const int valid = ROUTED ? g_cnt[e] : T;
    const int row0  = blockIdx.y * BM;
    if (row0 >= valid) return;
    const int col0  = blockIdx.x * 128;
    const int tid   = threadIdx.x, lane = tid & 31, wid = tid >> 5;
    const int wm    = wid >> 1, wn = wid & 1, grp = lane >> 2, tig = lane & 3;
    const uint32_t sb = s2u(sm);

    int*   stok = (int*)  (sm + 3 * DN_STAGE_U);
    float* sgw  = (float*)(sm + 3 * DN_STAGE_U + 128);
    if (ROUTED) {
        int i = row0 + tid; if (i >= valid) i = valid - 1;
        stok[tid] = g_tok[e * T + i];
        sgw[tid]  = g_gw [e * T + i];
    }
    __syncthreads();

    const uint32_t* ACT = ROUTED ? (g_act_e + (size_t)e * T * F) : g_act_s;
    const uint32_t* W2  = W2a + (size_t)e * H * F;

    const int r16 = tid >> 3, c4 = tid & 7;
    const uint32_t* abase = ACT + (size_t)(row0 + r16) * F + c4 * 4;  // rows >= valid: stale finite scratch, discarded
    const uint32_t* bbase = W2 + (size_t)(col0 + r16) * F + c4 * 4;
    const uint32_t aoff0 = (uint32_t)(r16 * SA + c4 * 4) * 4;
    const uint32_t rstep = 16u * SA * 4u;

    const int lrow = lane & 7;
    uint32_t aAddr[4];
    #pragma unroll
    for (int mt = 0; mt < 4; mt++) {
        int row = wm * 64 + mt * 16 + lrow + 8 * ((lane >> 3) & 1);
        aAddr[mt] = sb + (uint32_t)(row * SA + 4 * (lane >> 4)) * 4;
    }
    uint32_t bAddr[4];
    #pragma unroll
    for (int p = 0; p < 4; p++) {
        int row = wn * 64 + p * 16 + lrow + 8 * (lane >> 4);
        bAddr[p] = sb + A_BYTES + (uint32_t)(row * SA + 4 * ((lane >> 3) & 1)) * 4;
    }

    const int nch = F / BK;
    auto load_stage = [&](int c) {
        uint32_t dbase = sb + (uint32_t)(c % 3) * DN_STAGE_B;
        int k0 = c * BK;
        #pragma unroll
        for (int i = 0; i < 8; i++)
            cpa16(dbase + aoff0 + i * rstep, abase + (size_t)(16 * i) * F + k0);
        #pragma unroll
        for (int i = 0; i < 8; i++)
            cpa16(dbase + A_BYTES + aoff0 + i * rstep, bbase + (size_t)(16 * i) * F + k0);
    };

    float acc[4][8][4] = {};

    load_stage(0); CP_COMMIT();
    load_stage(1); CP_COMMIT();

    for (int c = 0; c < nch; ++c) {
        CP_WAIT1();
        __syncthreads();
        if (c + 2 < nch) load_stage(c + 2);
        CP_COMMIT();

        const uint32_t stof = (uint32_t)(c % 3) * DN_STAGE_B;
        #pragma unroll
        for (int j = 0; j < 4; j++) {
            uint32_t af[4][4];
            #pragma unroll
            for (int mt = 0; mt < 4; mt++) LDSM4(af[mt], aAddr[mt] + stof + 32u * j);
            uint32_t bf[4][4];
            #pragma unroll
            for (int p = 0; p < 4; p++) LDSM4(bf[p], bAddr[p] + stof + 32u * j);
            #pragma unroll
            for (int nt = 0; nt < 8; nt++) {
                const int pp = nt >> 1, q = nt & 1;
                uint32_t xb[2] = { bf[pp][2 * q], bf[pp][2 * q + 1] };
                #pragma unroll
                for (int mt = 0; mt < 4; mt++) mma8(acc[mt][nt], af[mt], xb);
            }
        }
    }

    #pragma unroll
    for (int mt = 0; mt < 4; mt++) {
        #pragma unroll
        for (int nt = 0; nt < 8; nt++) {
            int cA = col0 + wn * 64 + nt * 8 + 2 * tig;
            #pragma unroll
            for (int half = 0; half < 2; half++) {
                int rloc = wm * 64 + mt * 16 + grp + 8 * half;
                int r = row0 + rloc;
                if (r >= valid) continue;
                float v0 = acc[mt][nt][2 * half], v1 = acc[mt][nt][2 * half + 1];
                if (!ROUTED) {
                    float2 o; o.x = v0; o.y = v1;
                    *(float2*)(OUT + (size_t)r * H + cA) = o;
                } else {
                    int tok = stok[rloc]; float g = sgw[rloc];
                    float* dst = OUT + (size_t)tok * H + cA;
                    atomicAdd(dst,     g * v0);
                    atomicAdd(dst + 1, g * v1);
                }
            }
        }
    }
}

// ---------------- launch: forked multi-stream graph ----------------
extern "C" void kernel_launch(void* const* d_in, const int* in_sizes, int n_in,
                              void* d_out, int out_size) {
    const float* x    = (const float*)d_in[0];
    const float* gw   = (const float*)d_in[1];
    const float* bias = (const float*)d_in[2];
    const float* ws1  = (const float*)d_in[3];
    const float* ws2  = (const float*)d_in[4];
    const float* ws3  = (const float*)d_in[5];
    const float* we1  = (const float*)d_in[6];
    const float* we2  = (const float*)d_in[7];
    const float* we3  = (const float*)d_in[8];
    float* out = (float*)d_out;

    const int E  = in_sizes[2];
    const int Hd = in_sizes[1] / E;
    const int F  = in_sizes[3] / Hd;
    const int T  = in_sizes[0] / Hd;

    cudaFuncSetAttribute(up_mma<false>,   cudaFuncAttributeMaxDynamicSharedMemorySize, UP_SMEM);
    cudaFuncSetAttribute(up_mma<true>,    cudaFuncAttributeMaxDynamicSharedMemorySize, UP_SMEM);
    cudaFuncSetAttribute(down_mma<false>, cudaFuncAttributeMaxDynamicSharedMemorySize, DN_SMEM);
    cudaFuncSetAttribute(down_mma<true>,  cudaFuncAttributeMaxDynamicSharedMemorySize, DN_SMEM);

    uint32_t *p_cx, *p_cws1, *p_cws3, *p_cws2, *p_cwe1, *p_cwe3, *p_cwe2;
    float* p_routed;
    cudaGetSymbolAddress((void**)&p_cx,   c_x);
    cudaGetSymbolAddress((void**)&p_cws1, c_ws1);
    cudaGetSymbolAddress((void**)&p_cws3, c_ws3);
    cudaGetSymbolAddress((void**)&p_cws2, c_ws2);
    cudaGetSymbolAddress((void**)&p_cwe1, c_we1);
    cudaGetSymbolAddress((void**)&p_cwe3, c_we3);
    cudaGetSymbolAddress((void**)&p_cwe2, c_we2);
    cudaGetSymbolAddress((void**)&p_routed, g_routed);

    // streams/events created once (host-side resources; no device allocations)
    static cudaStream_t s1 = nullptr, s2 = nullptr;
    static cudaEvent_t e0 = nullptr, ex = nullptr, eg = nullptr, e1 = nullptr, e2 = nullptr;
    if (!s1) {
        cudaStreamCreateWithFlags(&s1, cudaStreamNonBlocking);
        cudaStreamCreateWithFlags(&s2, cudaStreamNonBlocking);
        cudaEventCreateWithFlags(&e0, cudaEventDisableTiming);
        cudaEventCreateWithFlags(&ex, cudaEventDisableTiming);
        cudaEventCreateWithFlags(&eg, cudaEventDisableTiming);
        cudaEventCreateWithFlags(&e1, cudaEventDisableTiming);
        cudaEventCreateWithFlags(&e2, cudaEventDisableTiming);
    }

    auto conv = [](cudaStream_t s, const float* in, uint32_t* o, size_t n) {
        conv_kernel<<<(unsigned)((n / 4 + 255) / 256), 256, 0, s>>>(in, o, n);
    };
    const size_t nOut = (size_t)T * Hd;

    // ---- fork from capture (default) stream ----
    zero_cnt_kernel<<<1, 32>>>();
    cudaEventRecord(e0, 0);
    cudaStreamWaitEvent(s1, e0, 0);
    cudaStreamWaitEvent(s2, e0, 0);

    // S0: gating (needs raw x only)
    gate_kernel<<<T, 256>>>(x, gw, bias, T, Hd, E);
    cudaEventRecord(eg, 0);

    // S1: shared-expert chain
    conv(s1, x,   p_cx,   (size_t)T * Hd);
    cudaEventRecord(ex, s1);                       // conv_x done (needed by up_e)
    conv(s1, ws1, p_cws1, (size_t)F * Hd);
    conv(s1, ws3, p_cws3, (size_t)F * Hd);
    conv(s1, ws2, p_cws2, (size_t)Hd * F);
    {
        dim3 blk(128);
        up_mma<false><<<dim3(F / 64, T / BM), blk, UP_SMEM, s1>>>(p_cx, p_cws1, p_cws3, T, Hd, F);
        down_mma<false><<<dim3(Hd / 128, T / BM), blk, DN_SMEM, s1>>>(p_cws2, out, T, Hd, F);
    }
    cudaEventRecord(e1, s1);

    // S2: routed-expert chain (accumulates into g_routed)
    zero_routed_kernel<<<(unsigned)((nOut / 4 + 255) / 256), 256, 0, s2>>>(nOut);
    conv(s2, we1, p_cwe1, (size_t)E * F * Hd);
    conv(s2, we3, p_cwe3, (size_t)E * F * Hd);
    conv(s2, we2, p_cwe2, (size_t)E * Hd * F);
    cudaStreamWaitEvent(s2, ex, 0);                // need converted x
    cudaStreamWaitEvent(s2, eg, 0);                // need routing lists
    {
        dim3 blk(128);
        up_mma<true><<<dim3(F / 64, T / BM, E), blk, UP_SMEM, s2>>>(p_cx, p_cwe1, p_cwe3, T, Hd, F);
        down_mma<true><<<dim3(Hd / 128, T / BM, E), blk, DN_SMEM, s2>>>(p_cwe2, p_routed, T, Hd, F);
    }
    cudaEventRecord(e2, s2);

    // ---- join on capture stream ----
    cudaStreamWaitEvent(0, e1, 0);
    cudaStreamWaitEvent(0, e2, 0);
    final_add_kernel<<<(unsigned)((nOut / 4 + 255) / 256), 256>>>(out, nOut);
}